// round 15
// baseline (speedup 1.0000x reference)
#include <cuda_runtime.h>
#include <cuda_bf16.h>
#include <math.h>
#include <stdint.h>

#define NB     2
#define CIN    320
#define TT0    4
#define HW0    196
#define VPLANE 50176
#define VF     8
#define CDIM   768
#define TD     4
#define HH     53
#define HWD    2809
#define MPROJ  22472          // NB*TD*HWD
#define KPROJ  2304
#define NTOK   32
#define KF     2841
#define KFP    2880           // padded to multiple of 16
#define BT3    6
#define MROWS  4608           // BT3*CDIM
#define EPSBN  1e-5

// ---------------- static scratch ----------------
__device__ float  g_scaleA[CIN], g_shiftA[CIN];
__device__ float  g_v[(size_t)NB*3*VF*VPLANE];
__device__ double g_redV[3*32*2];
__device__ float  g_scaleP[3], g_shiftP[3];
__device__ float  g_xp [(size_t)MPROJ*CDIM];
__device__ float  g_pos[(size_t)MPROJ*CDIM];
__device__ double g_sumT[CDIM], g_sumsqT[CDIM], g_sumC[CDIM], g_sumsqC[CDIM];
__device__ float  g_scaleT[CDIM], g_shiftT[CDIM];
__device__ float  g_scaleC[CDIM], g_shiftC[CDIM];
__device__ float  g_d [(size_t)NB*HWD*CDIM];
__device__ float  g_sel[(size_t)NB*HWD*NTOK];
__device__ float  g_selmax[NB*NTOK];
__device__ float  g_tem [NB*NTOK*CDIM];
__device__ float  g_kpT [(size_t)BT3*HWD*CDIM];
__device__ float  g_score[(size_t)BT3*NTOK*HWD];
__device__ float  g_smax[BT3*NTOK];
// bf16 hi/lo operand buffers
__device__ __nv_bfloat16 g_colh[(size_t)MPROJ*KPROJ], g_coll[(size_t)MPROJ*KPROJ];
__device__ __nv_bfloat16 g_pwh[(size_t)CDIM*KPROJ],   g_pwl[(size_t)CDIM*KPROJ];
__device__ __nv_bfloat16 g_kmh[(size_t)MROWS*KFP],    g_kml[(size_t)MROWS*KFP];
__device__ __nv_bfloat16 g_f1h[(size_t)KF*KFP],       g_f1l[(size_t)KF*KFP];
__device__ __nv_bfloat16 g_f2h[(size_t)HWD*KFP],      g_f2l[(size_t)HWD*KFP];
__device__ __nv_bfloat16 g_hh [(size_t)MROWS*KFP],    g_hl [(size_t)MROWS*KFP];

// ---------------- helpers ----------------
__device__ __forceinline__ uint32_t smem_u32(const void* p) {
    uint32_t a;
    asm("{ .reg .u64 t; cvta.to.shared.u64 t, %1; cvt.u32.u64 %0, t; }" : "=r"(a) : "l"(p));
    return a;
}
__device__ __forceinline__ void ldsm4(uint32_t* r, uint32_t addr) {
    asm volatile("ldmatrix.sync.aligned.m8n8.x4.shared.b16 {%0,%1,%2,%3}, [%4];"
        : "=r"(r[0]), "=r"(r[1]), "=r"(r[2]), "=r"(r[3]) : "r"(addr));
}
__device__ __forceinline__ void mma16816(float* c, const uint32_t* a, uint32_t b0, uint32_t b1) {
    asm volatile("mma.sync.aligned.m16n8k16.row.col.f32.bf16.bf16.f32 "
        "{%0,%1,%2,%3},{%4,%5,%6,%7},{%8,%9},{%0,%1,%2,%3};"
        : "+f"(c[0]), "+f"(c[1]), "+f"(c[2]), "+f"(c[3])
        : "r"(a[0]), "r"(a[1]), "r"(a[2]), "r"(a[3]), "r"(b0), "r"(b1));
}
__device__ __forceinline__ void cpa16(uint32_t dst, const void* src, int srcsize) {
    asm volatile("cp.async.cg.shared.global [%0], [%1], 16, %2;"
        :: "r"(dst), "l"(src), "r"(srcsize) : "memory");
}
#define CP_COMMIT() asm volatile("cp.async.commit_group;" ::: "memory")
#define CP_WAIT1()  asm volatile("cp.async.wait_group 1;" ::: "memory")
#define CP_WAIT0()  asm volatile("cp.async.wait_group 0;" ::: "memory")

__device__ __forceinline__ void split_bf16(float x, __nv_bfloat16 &h, __nv_bfloat16 &l) {
    h = __float2bfloat16(x);
    l = __float2bfloat16(x - __bfloat162float(h));
}

// ================= HMMA bf16x3 GEMM (128x128 block, 64x32 warp tile, cp.async x3) =================
// EXACT copy of the 3931.6us R10 kernel.
#define LDSE   24                    // smem row stride (bf16) = 48 B
#define MATB   (128*48)              // 6144 B per matrix tile
#define STGB   (4*MATB)              // 24576 B per stage
__global__ __launch_bounds__(256, 2) void k_hgemm(
    const __nv_bfloat16* __restrict__ Ah, const __nv_bfloat16* __restrict__ Al, int lda,
    const __nv_bfloat16* __restrict__ Bh, const __nv_bfloat16* __restrict__ Bl, int ldb,
    const float* __restrict__ bias, float* __restrict__ Cf,
    __nv_bfloat16* __restrict__ Oh, __nv_bfloat16* __restrict__ Ol,
    int M, int N, int K, int ldc, int mode)
{
    extern __shared__ char smem[];
    const uint32_t sbase = smem_u32(smem);
    const int tid = threadIdx.x;
    const int wid = tid >> 5, lane = tid & 31;
    const int m0 = blockIdx.y * 128, n0 = blockIdx.x * 128;
    const int wm = wid & 1, wn = wid >> 1;   // warp tile 64(m) x 32(n)

    // ---- loaders: mat = tid>>6 (0:Ah 1:Al 2:Bh 3:Bl), 2 rows each ----
    const int mat = tid >> 6;
    const int rr  = (tid & 63) << 1;
    const __nv_bfloat16* src; int ld, base, lim;
    if      (mat == 0) { src = Ah; ld = lda; base = m0; lim = M; }
    else if (mat == 1) { src = Al; ld = lda; base = m0; lim = M; }
    else if (mat == 2) { src = Bh; ld = ldb; base = n0; lim = N; }
    else               { src = Bl; ld = ldb; base = n0; lim = N; }
    const int sz0 = ((base + rr)     < lim) ? 16 : 0;
    const int sz1 = ((base + rr + 1) < lim) ? 16 : 0;
    const char* p0 = (const char*)(src + (size_t)(sz0 ? base + rr     : 0) * ld);
    const char* p1 = (const char*)(src + (size_t)(sz1 ? base + rr + 1 : 0) * ld);
    const uint32_t d0 = sbase + mat * MATB + rr * 48;
    const uint32_t d1 = d0 + 48;

    // ---- fragment smem offsets ----
    const uint32_t afo = (uint32_t)(((wm * 64 + (lane & 15)) * LDSE + (lane >> 4) * 8) * 2);
    const uint32_t bfo = (uint32_t)(((wn * 32 + (lane & 15)) * LDSE + (lane >> 4) * 8) * 2);

    float acc[4][4][4];
    #pragma unroll
    for (int i = 0; i < 4; i++)
        #pragma unroll
        for (int j = 0; j < 4; j++)
            #pragma unroll
            for (int q = 0; q < 4; q++) acc[i][j][q] = 0.f;

    const int KT = K >> 4;

    // prologue: stages 0 and 1
    cpa16(d0, p0, sz0); cpa16(d0 + 16, p0 + 16, sz0);
    cpa16(d1, p1, sz1); cpa16(d1 + 16, p1 + 16, sz1);
    CP_COMMIT();
    if (KT > 1) {
        cpa16(d0 + STGB, p0 + 32, sz0); cpa16(d0 + STGB + 16, p0 + 48, sz0);
        cpa16(d1 + STGB, p1 + 32, sz1); cpa16(d1 + STGB + 16, p1 + 48, sz1);
    }
    CP_COMMIT();

    int buf = 0;
    for (int kt = 0; kt < KT; kt++) {
        CP_WAIT1();
        __syncthreads();
        const uint32_t st = sbase + buf * STGB;
        uint32_t bh[2][4], bl[2][4];
        #pragma unroll
        for (int t = 0; t < 2; t++) {
            ldsm4(bh[t], st + 2*MATB + bfo + t * (16 * 48));
            ldsm4(bl[t], st + 3*MATB + bfo + t * (16 * 48));
        }
        #pragma unroll
        for (int i = 0; i < 4; i++) {
            uint32_t ah4[4], al4[4];
            ldsm4(ah4, st + afo + i * (16 * 48));
            ldsm4(al4, st + MATB + afo + i * (16 * 48));
            #pragma unroll
            for (int j = 0; j < 4; j++) {
                const int t = j >> 1, o = j & 1;
                mma16816(acc[i][j], ah4, bh[t][o], bh[t][2 + o]);
                mma16816(acc[i][j], ah4, bl[t][o], bl[t][2 + o]);
                mma16816(acc[i][j], al4, bh[t][o], bh[t][2 + o]);
            }
        }
        if (kt + 2 < KT) {
            const int nb = (buf + 2) % 3;
            const size_t ko = (size_t)(kt + 2) * 32;
            const uint32_t w0 = d0 + nb * STGB, w1 = d1 + nb * STGB;
            cpa16(w0, p0 + ko, sz0); cpa16(w0 + 16, p0 + ko + 16, sz0);
            cpa16(w1, p1 + ko, sz1); cpa16(w1 + 16, p1 + ko + 16, sz1);
        }
        CP_COMMIT();
        buf = (buf + 1) % 3;
    }
    CP_WAIT0();
    __syncthreads();

    // ---- epilogue: stage acc -> smf[128][129] ----
    float* smf = (float*)smem;
    #pragma unroll
    for (int i = 0; i < 4; i++) {
        const int mr = wm * 64 + i * 16 + (lane >> 2);
        #pragma unroll
        for (int j = 0; j < 4; j++) {
            const int nc = wn * 32 + j * 8 + (lane & 3) * 2;
            smf[mr * 129 + nc]           = acc[i][j][0];
            smf[mr * 129 + nc + 1]       = acc[i][j][1];
            smf[(mr + 8) * 129 + nc]     = acc[i][j][2];
            smf[(mr + 8) * 129 + nc + 1] = acc[i][j][3];
        }
    }
    __syncthreads();

    if (mode == 0) {
        for (int idx = tid; idx < 128 * 128; idx += 256) {
            const int mm = idx >> 7, nn = idx & 127;
            const int m = m0 + mm, n = n0 + nn;
            if (m < M && n < N)
                Cf[(size_t)m * ldc + n] = smf[mm * 129 + nn] + (bias ? bias[n] : 0.f);
        }
    } else if (mode == 1) {
        for (int idx = tid; idx < 128 * 128; idx += 256) {
            const int mm = idx >> 7, nn = idx & 127;
            const int m = m0 + mm, n = n0 + nn;
            if (m < M && n < ldc) {
                float v = 0.f;
                if (n < N) {
                    v = smf[mm * 129 + nn] + bias[n];
                    v = 0.5f * v * (1.f + erff(v * 0.70710678118654752f));
                }
                __nv_bfloat16 h, l; split_bf16(v, h, l);
                Oh[(size_t)m * ldc + n] = h;
                Ol[(size_t)m * ldc + n] = l;
            }
        }
    } else {
        const int z2 = m0 / CDIM, cbase = m0 % CDIM;
        for (int idx = tid; idx < 128 * 128; idx += 256) {
            const int mm = idx & 127, jn = idx >> 7;
            const int n = n0 + jn;
            if (n < N)
                Cf[((size_t)z2 * HWD + n) * CDIM + cbase + mm] =
                    smf[mm * 129 + jn] + bias[n];
        }
    }
}

// ---------------- dedicated score GEMM ----------------
__global__ __launch_bounds__(256) void k_score() {
    const int z = blockIdx.y, hw0 = blockIdx.x * 128;
    const int b = z / 3;
    const int tid = threadIdx.x;
    const int hwl = tid & 127, ng = tid >> 7;
    __shared__ float tems[32][64];
    __shared__ float kps[128][65];
    float acc[16];
    #pragma unroll
    for (int i = 0; i < 16; i++) acc[i] = 0.f;
    const int hw = hw0 + hwl;

    for (int k0 = 0; k0 < CDIM; k0 += 64) {
        __syncthreads();
        for (int i = tid; i < 32 * 64; i += 256) {
            int n = i >> 6, c = i & 63;
            tems[n][c] = g_tem[((size_t)b * NTOK + n) * CDIM + k0 + c];
        }
        for (int i = tid; i < 128 * 16; i += 256) {
            int r = i >> 4, c4 = (i & 15) << 2;
            float4 v = (hw0 + r < HWD)
                ? *(const float4*)&g_kpT[((size_t)z * HWD + hw0 + r) * CDIM + k0 + c4]
                : make_float4(0.f, 0.f, 0.f, 0.f);
            kps[r][c4] = v.x; kps[r][c4+1] = v.y; kps[r][c4+2] = v.z; kps[r][c4+3] = v.w;
        }
        __syncthreads();
        #pragma unroll 16
        for (int kk = 0; kk < 64; kk++) {
            float kv = kps[hwl][kk];
            #pragma unroll
            for (int nn = 0; nn < 16; nn++)
                acc[nn] = fmaf(tems[ng * 16 + nn][kk], kv, acc[nn]);
        }
    }
    if (hw < HWD) {
        #pragma unroll
        for (int nn = 0; nn < 16; nn++)
            g_score[((size_t)z * NTOK + ng * 16 + nn) * HWD + hw] = acc[nn];
    }
}

// ---------------- zero accumulators ----------------
__global__ void k_zero() {
    int i = threadIdx.x;
    if (i < CDIM) { g_sumT[i]=0.0; g_sumsqT[i]=0.0; g_sumC[i]=0.0; g_sumsqC[i]=0.0; }
}

// ---------------- BN over x (320 ch) ----------------
__global__ void k_bn_a(const float* __restrict__ x, const float* __restrict__ g,
                       const float* __restrict__ b) {
    int c = blockIdx.x;
    double s = 0.0, s2 = 0.0;
    for (int i = threadIdx.x; i < NB*TT0*HW0; i += blockDim.x) {
        int bb = i / (TT0*HW0), r = i % (TT0*HW0);
        float v = x[((size_t)(bb*CIN + c))*(TT0*HW0) + r];
        s += v; s2 += (double)v * v;
    }
    __shared__ double sh[256], sh2[256];
    sh[threadIdx.x] = s; sh2[threadIdx.x] = s2;
    __syncthreads();
    for (int o = 128; o > 0; o >>= 1) {
        if (threadIdx.x < o) { sh[threadIdx.x] += sh[threadIdx.x+o]; sh2[threadIdx.x] += sh2[threadIdx.x+o]; }
        __syncthreads();
    }
    if (threadIdx.x == 0) {
        double n = (double)(NB*TT0*HW0);
        double mean = sh[0]/n, var = sh2[0]/n - mean*mean;
        float sc = (float)((double)g[c] / sqrt(var + EPSBN));
        g_scaleA[c] = sc;
        g_shiftA[c] = b[c] - (float)mean * sc;
    }
}

// ---------------- tconv + relu6 + residual -> g_v (8 positions/block) ----------------
__global__ __launch_bounds__(256) void k_tconv(
    const float* __restrict__ x, const float* __restrict__ tw,
    const float* __restrict__ tb, const float* __restrict__ ori) {
    __shared__ float xs[8][CIN];
    int tid = threadIdx.x;
    for (int idx = tid; idx < 8*CIN; idx += 256) {
        int p = idx / CIN, i = idx % CIN;
        int lin = blockIdx.x * 8 + p;
        int w = lin % 14, h = (lin/14) % 14, t = (lin/196) % TT0, bb = lin/(196*TT0);
        xs[p][i] = x[((size_t)(bb*CIN+i)*TT0 + t)*HW0 + h*14 + w] * g_scaleA[i] + g_shiftA[i];
    }
    __syncthreads();
    for (int jj = tid; jj < 1536; jj += 256) {
        float a[8];
        #pragma unroll
        for (int p = 0; p < 8; p++) a[p] = 0.f;
        const float* wp = tw + jj;
        #pragma unroll 4
        for (int i = 0; i < CIN; i++) {
            float wv = *wp; wp += 1536;
            #pragma unroll
            for (int p = 0; p < 8; p++) a[p] = fmaf(xs[p][i], wv, a[p]);
        }
        int o = jj >> 9, rem = jj & 511;
        int k = rem >> 8, p = (rem >> 4) & 15, q = rem & 15;
        float bias = tb[o];
        #pragma unroll
        for (int pp = 0; pp < 8; pp++) {
            int lin = blockIdx.x * 8 + pp;
            int w = lin % 14, h = (lin/14) % 14, t = (lin/196) % TT0, bb = lin/(196*TT0);
            float val = fminf(fmaxf(a[pp] + bias, 0.f), 6.f);
            size_t oidx = ((size_t)(bb*3+o)*VF + (2*t+k))*VPLANE + (16*h+p)*224 + (16*w+q);
            g_v[oidx] = val + ori[oidx];
        }
    }
}

// ---------------- BN stats of v (3 ch), 4-way accumulator chains ----------------
__global__ void k_bnv_part() {
    int ch = blockIdx.x, part = blockIdx.y;
    const int per = (NB*VF*VPLANE) / 32;
    double s[4] = {0,0,0,0}, s2[4] = {0,0,0,0};
    int base = part * per;
    for (int i = threadIdx.x; i < per; i += blockDim.x * 4) {
        #pragma unroll
        for (int u = 0; u < 4; u++) {
            int ii = i + u * blockDim.x;
            if (ii < per) {
                int gi = base + ii;
                int b = gi / (VF*VPLANE), r = gi % (VF*VPLANE);
                float v = g_v[((size_t)(b*3+ch))*VF*VPLANE + r];
                s[u] += v; s2[u] += (double)v * v;
            }
        }
    }
    double st = (s[0] + s[1]) + (s[2] + s[3]);
    double st2 = (s2[0] + s2[1]) + (s2[2] + s2[3]);
    __shared__ double sh[256], sh2[256];
    sh[threadIdx.x] = st; sh2[threadIdx.x] = st2;
    __syncthreads();
    for (int o = 128; o > 0; o >>= 1) {
        if (threadIdx.x < o) { sh[threadIdx.x] += sh[threadIdx.x+o]; sh2[threadIdx.x] += sh2[threadIdx.x+o]; }
        __syncthreads();
    }
    if (threadIdx.x == 0) { g_redV[(ch*32+part)*2] = sh[0]; g_redV[(ch*32+part)*2+1] = sh2[0]; }
}
__global__ void k_bnv_final(const float* __restrict__ g, const float* __restrict__ b) {
    int ch = blockIdx.x;
    double s  = g_redV[(ch*32 + threadIdx.x)*2];
    double s2 = g_redV[(ch*32 + threadIdx.x)*2 + 1];
    for (int o = 16; o > 0; o >>= 1) {
        s  += __shfl_down_sync(0xffffffffu, s,  o);
        s2 += __shfl_down_sync(0xffffffffu, s2, o);
    }
    if (threadIdx.x == 0) {
        double n = (double)(NB*VF*VPLANE);
        double mean = s/n, var = s2/n - mean*mean;
        float sc = (float)((double)g[ch] / sqrt(var + EPSBN));
        g_scaleP[ch] = sc;
        g_shiftP[ch] = b[ch] - (float)mean * sc;
    }
}

// ---------------- im2col -> bf16 hi/lo (BN folded, zero t-pad) ----------------
__global__ void k_im2col() {
    size_t idx = (size_t)blockIdx.x * 256 + threadIdx.x;
    if (idx >= (size_t)MPROJ * 576) return;
    int m  = (int)(idx / 576);
    int k4 = (int)(idx % 576) * 4;
    int c  = k4 / 768;
    int kt = (k4 % 768) / 256;
    int p  = (k4 % 256) / 16;
    int q  = k4 % 16;
    int w = m % HH, h = (m/HH) % HH, t = (m/HWD) % TD, b = m / (TD*HWD);
    int it = 2*t + kt - 1;
    float4 o;
    if (it < 0 || it > 7) {
        o = make_float4(0.f, 0.f, 0.f, 0.f);
    } else {
        const float* src = g_v + ((size_t)(b*3+c)*VF + it)*VPLANE + (4*h+p)*224 + (4*w+q);
        float4 v = *(const float4*)src;
        float sc = g_scaleP[c], sh = g_shiftP[c];
        o = make_float4(v.x*sc+sh, v.y*sc+sh, v.z*sc+sh, v.w*sc+sh);
    }
    __nv_bfloat16 h0,h1,h2,h3,l0,l1,l2,l3;
    split_bf16(o.x,h0,l0); split_bf16(o.y,h1,l1); split_bf16(o.z,h2,l2); split_bf16(o.w,h3,l3);
    uint2 ph, pl;
    ph.x = (uint32_t)__bfloat16_as_ushort(h0) | ((uint32_t)__bfloat16_as_ushort(h1) << 16);
    ph.y = (uint32_t)__bfloat16_as_ushort(h2) | ((uint32_t)__bfloat16_as_ushort(h3) << 16);
    pl.x = (uint32_t)__bfloat16_as_ushort(l0) | ((uint32_t)__bfloat16_as_ushort(l1) << 16);
    pl.y = (uint32_t)__bfloat16_as_ushort(l2) | ((uint32_t)__bfloat16_as_ushort(l3) << 16);
    *(uint2*)(g_colh + (size_t)m*KPROJ + k4) = ph;
    *(uint2*)(g_coll + (size_t)m*KPROJ + k4) = pl;
}

// ---------------- fp32 -> bf16 hi/lo weight convert with K padding ----------------
__global__ void k_cvtpad(const float* __restrict__ src, __nv_bfloat16* __restrict__ dh,
                         __nv_bfloat16* __restrict__ dl, int rows, int kin, int kout) {
    size_t idx = (size_t)blockIdx.x * 256 + threadIdx.x;
    if (idx >= (size_t)rows * kout) return;
    int rr = (int)(idx / kout), k = (int)(idx % kout);
    float v = (k < kin) ? src[(size_t)rr * kin + k] : 0.f;
    __nv_bfloat16 h, l; split_bf16(v, h, l);
    dh[idx] = h; dl[idx] = l;
}

// ---------------- pos conv: depthwise 3x3x3 pad 1 on raw xp ----------------
__global__ __launch_bounds__(768) void k_pos(const float* __restrict__ pw,
                                             const float* __restrict__ pb) {
    int h = blockIdx.x, t = blockIdx.y, b = blockIdx.z;
    int c = threadIdx.x;
    float w27[27];
    #pragma unroll
    for (int i = 0; i < 27; i++) w27[i] = pw[c*27 + i];
    float bias = pb[c];
    float prv[9], cur[9], nxt[9];
    #pragma unroll
    for (int j = 0; j < 9; j++) { prv[j] = 0.f; cur[j] = 0.f; }
    #pragma unroll
    for (int j = 0; j < 9; j++) {
        int dt = j/3 - 1, dh = j%3 - 1;
        int tt = t + dt, hh = h + dh;
        cur[j] = (tt >= 0 && tt < TD && hh >= 0 && hh < HH)
                 ? g_xp[(((size_t)(b*TD+tt)*HWD) + hh*HH + 0)*CDIM + c] : 0.f;
    }
    for (int w = 0; w < HH; w++) {
        #pragma unroll
        for (int j = 0; j < 9; j++) {
            int dt = j/3 - 1, dh = j%3 - 1;
            int tt = t + dt, hh = h + dh;
            nxt[j] = (w+1 < HH && tt >= 0 && tt < TD && hh >= 0 && hh < HH)
                     ? g_xp[(((size_t)(b*TD+tt)*HWD) + hh*HH + (w+1))*CDIM + c] : 0.f;
        }
        float acc = bias;
        #pragma unroll
        for (int j = 0; j < 9; j++) {
            acc = fmaf(prv[j], w27[j*3+0], acc);
            acc = fmaf(cur[j], w27[j*3+1], acc);
            acc = fmaf(nxt[j], w27[j*3+2], acc);
        }
        g_pos[(((size_t)(b*TD+t)*HWD) + h*HH + w)*CDIM + c] = acc;
        #pragma unroll
        for (int j = 0; j < 9; j++) { prv[j] = cur[j]; cur[j] = nxt[j]; }
    }
}

// ---------------- merged BN stats ----------------
__global__ void k_bnstat() {
    int tid = threadIdx.x;
    double sc_[3] = {0,0,0}, sc2[3] = {0,0,0};
    double st_[3] = {0,0,0}, st2[3] = {0,0,0};
    int r0 = blockIdx.x * 256;
    for (int i = 0; i < 256; i++) {
        int r = r0 + i;
        if (r >= MPROJ) break;
        bool isT0 = ((r / HWD) % TD) == 0;
        size_t base = (size_t)r * CDIM;
        #pragma unroll
        for (int k = 0; k < 3; k++) {
            float v = g_xp[base + tid + 256*k];
            double dv = (double)v;
            sc_[k] += dv; sc2[k] += dv * dv;
            if (isT0) { st_[k] += dv; st2[k] += dv * dv; }
        }
    }
    #pragma unroll
    for (int k = 0; k < 3; k++) {
        atomicAdd(&g_sumC[tid + 256*k],   sc_[k]);
        atomicAdd(&g_sumsqC[tid + 256*k], sc2[k]);
        atomicAdd(&g_sumT[tid + 256*k],   st_[k]);
        atomicAdd(&g_sumsqT[tid + 256*k], st2[k]);
    }
}
__global__ void k_bnfin(const float* gt, const float* bt,
                        const float* gc, const float* bc) {
    int c = threadIdx.x;
    {
        double n = (double)(NB*HWD);
        double mean = g_sumT[c]/n, var = g_sumsqT[c]/n - mean*mean;
        float sc = (float)((double)gt[c] / sqrt(var + EPSBN));
        g_scaleT[c] = sc; g_shiftT[c] = bt[c] - (float)mean * sc;
    }
    {
        double n = (double)MPROJ;
        double mean = g_sumC[c]/n, var = g_sumsqC[c]/n - mean*mean;
        float sc = (float)((double)gc[c] / sqrt(var + EPSBN));
        g_scaleC[c] = sc; g_shiftC[c] = bc[c] - (float)mean * sc;
    }
}

// ---------------- token-selector depthwise 3x3 + hardswish (BN_t inline) ----------------
__global__ __launch_bounds__(768) void k_dw(const float* __restrict__ dw,
                                            const float* __restrict__ db) {
    int h = blockIdx.x, b = blockIdx.y;
    int c = threadIdx.x;
    float w9[9];
    #pragma unroll
    for (int i = 0; i < 9; i++) w9[i] = dw[c*9 + i];
    float bias = db[c];
    const float scT = g_scaleT[c], shT = g_shiftT[c];
    const size_t xb0 = (size_t)(b*TD) * HWD;   // frame-0 base row of xp
    float prv[3], cur[3], nxt[3];
    #pragma unroll
    for (int j = 0; j < 3; j++) prv[j] = 0.f;
    #pragma unroll
    for (int j = 0; j < 3; j++) {
        int hh = h + j - 1;
        cur[j] = (hh >= 0 && hh < HH)
                 ? fmaf(g_xp[(xb0 + hh*HH + 0)*CDIM + c], scT, shT) : 0.f;
    }
    for (int w = 0; w < HH; w++) {
        #pragma unroll
        for (int j = 0; j < 3; j++) {
            int hh = h + j - 1;
            nxt[j] = (w+1 < HH && hh >= 0 && hh < HH)
                     ? fmaf(g_xp[(xb0 + hh*HH + (w+1))*CDIM + c], scT, shT) : 0.f;
        }
        float acc = bias;
        #pragma unroll
        for (int j = 0; j < 3; j++) {
            acc = fmaf(prv[j], w9[j*3+0], acc);
            acc = fmaf(cur[j], w9[j*3+1], acc);
            acc = fmaf(nxt[j], w9[j*3+2], acc);
        }
        float hs = acc * fminf(fmaxf(acc + 3.f, 0.f), 6.f) * (1.f/6.f);
        g_d[((size_t)b*HWD + h*HH + w)*CDIM + c] = hs;
        #pragma unroll
        for (int j = 0; j < 3; j++) { prv[j] = cur[j]; cur[j] = nxt[j]; }
    }
}

// ---------------- sel = pw(d) ----------------
__global__ void k_sel(const float* __restrict__ pww, const float* __restrict__ pwb) {
    int hw = blockIdx.x, b = blockIdx.y;
    __shared__ float ds[CDIM];
    for (int c = threadIdx.x; c < CDIM; c += 256)
        ds[c] = g_d[((size_t)b*HWD + hw)*CDIM + c];
    __syncthreads();
    int n = threadIdx.x >> 3, sub = threadIdx.x & 7;
    float acc = 0.f;
    for (int c = sub; c < CDIM; c += 8)
        acc = fmaf(ds[c], pww[n*CDIM + c], acc);
    acc += __shfl_xor_sync(0xffffffffu, acc, 1);
    acc += __shfl_xor_sync(0xffffffffu, acc, 2);
    acc += __shfl_xor_sync(0xffffffffu, acc, 4);
    if (sub == 0) g_sel[((size_t)b*HWD + hw)*NTOK + n] = acc + pwb[n];
}

__global__ void k_selmax() {
    int n = blockIdx.x, b = blockIdx.y;
    float m = -3.4e38f;
    for (int hw = threadIdx.x; hw < HWD; hw += 256)
        m = fmaxf(m, g_sel[((size_t)b*HWD + hw)*NTOK + n]);
    __shared__ float sh[256];
    sh[threadIdx.x] = m;
    __syncthreads();
    for (int o = 128; o > 0; o >>= 1) {
        if (threadIdx.x < o) sh[threadIdx.x] = fmaxf(sh[threadIdx.x], sh[threadIdx.x+o]);
        __syncthreads();
    }
    if (threadIdx.x == 0) g_selmax[b*NTOK + n] = sh[0];
}

// ---------------- tem gather (BN_t inline for feat) ----------------
__global__ void k_temgather(float* __restrict__ out, float* __restrict__ outp) {
    int n = blockIdx.x, b = blockIdx.y;
    __shared__ unsigned char flag[HWD];
    float mx = g_selmax[b*NTOK + n];
    for (int hw = threadIdx.x; hw < HWD; hw += 256)
        flag[hw] = (g_sel[((size_t)b*HWD + hw)*NTOK + n] == mx) ? 1 : 0;
    __syncthreads();
    int c0 = threadIdx.x, c1 = threadIdx.x + 256, c2 = threadIdx.x + 512;
    const float sc0 = g_scaleT[c0], sh0 = g_shiftT[c0];
    const float sc1 = g_scaleT[c1], sh1 = g_shiftT[c1];
    const float sc2 = g_scaleT[c2], sh2 = g_shiftT[c2];
    float a0=0,a1=0,a2=0, p0=0,p1=0,p2=0;
    for (int hw = 0; hw < HWD; hw++) {
        if (flag[hw]) {
            size_t pb = ((size_t)(b*TD)*HWD + hw)*CDIM;
            a0 += fmaf(g_xp[pb+c0], sc0, sh0);
            a1 += fmaf(g_xp[pb+c1], sc1, sh1);
            a2 += fmaf(g_xp[pb+c2], sc2, sh2);
            p0 += g_pos[pb+c0]; p1 += g_pos[pb+c1]; p2 += g_pos[pb+c2];
        }
    }
    size_t tb = ((size_t)b*NTOK + n)*CDIM;
    g_tem[tb+c0]=a0; g_tem[tb+c1]=a1; g_tem[tb+c2]=a2;
    size_t ob = ((size_t)(b*TD + 0)*NTOK + n)*CDIM;
    out[ob+c0]=a0; out[ob+c1]=a1; out[ob+c2]=a2;
    outp[ob+c0]=p0; outp[ob+c1]=p1; outp[ob+c2]=p2;
}

// ---------------- build kmat hi/lo [z*768+c][j], ld=KFP ----------------
__global__ void k_kmat() {
    int j = blockIdx.x * 128 + threadIdx.x;
    if (j >= KFP) return;
    int c = blockIdx.y, z = blockIdx.z;
    int b = z / 3, t = z % 3;
    float v;
    if (j < NTOK)      v = g_tem[((size_t)b*NTOK + j)*CDIM + c];
    else if (j < KF)   v = g_xp[((size_t)(b*TD + t + 1)*HWD + (j - NTOK))*CDIM + c]
                           * g_scaleC[c] + g_shiftC[c];
    else               v = 0.f;
    __nv_bfloat16 h, l; split_bf16(v, h, l);
    size_t o = ((size_t)z*CDIM + c)*KFP + j;
    g_kmh[o] = h; g_kml[o] = l;
}

// ---------------- score max ----------------
__global__ void k_scoremax() {
    int n = blockIdx.x, z = blockIdx.y;
    float m = -3.4e38f;
    for (int hw = threadIdx.x; hw < HWD; hw += 256)
        m = fmaxf(m, g_score[((size_t)z*NTOK + n)*HWD + hw]);
    __shared__ float sh[256];
    sh[threadIdx.x] = m;
    __syncthreads();
    for (int o = 128; o > 0; o >>= 1) {
        if (threadIdx.x < o) sh[threadIdx.x] = fmaxf(sh[threadIdx.x], sh[threadIdx.x+o]);
        __syncthreads();
    }
    if (threadIdx.x == 0) g_smax[z*NTOK + n] = sh[0];
}

// ---------------- route gather -> out frames 1..3 ----------------
__global__ void k_route(float* __restrict__ out, float* __restrict__ outp) {
    int n = blockIdx.x, z = blockIdx.y;
    int b = z / 3, t = z % 3;
    __shared__ unsigned char flag[HWD];
    float mx = g_smax[z*NTOK + n];
    for (int hw = threadIdx.x; hw < HWD; hw += 256)
        flag[hw] = (g_score[((size_t)z*NTOK + n)*HWD + hw] == mx) ? 1 : 0;
    __syncthreads();
    int c0 = threadIdx.x, c1 = threadIdx.x + 256, c2 = threadIdx.x + 512;
    float s0=0,s1=0,s2=0, p0=0,p1=0,p2=0;
    int cnt = 0;
    for (int hw = 0; hw < HWD; hw++) {
        if (flag[hw]) {
            size_t xb = ((size_t)(b*TD + t + 1)*HWD + hw)*CDIM;
            s0 += g_xp[xb+c0]; s1 += g_xp[xb+c1]; s2 += g_xp[xb+c2];
            p0 += g_pos[xb+c0]; p1 += g_pos[xb+c1]; p2 += g_pos[xb+c2];
            cnt++;
        }
    }
    float fc = (float)cnt;
    size_t ob = ((size_t)(b*TD + t + 1)*NTOK + n)*CDIM;
    out[ob+c0] = g_scaleC[c0]*s0 + fc*g_shiftC[c0];
    out[ob+c1] = g_scaleC[c1]*s1 + fc*g_shiftC[c1];
    out[ob+c2] = g_scaleC[c2]*s2 + fc*g_shiftC[c2];
    outp[ob+c0] = p0; outp[ob+c1] = p1; outp[ob+c2] = p2;
}

// ---------------- launch ----------------
extern "C" void kernel_launch(void* const* d_in, const int* in_sizes, int n_in,
                              void* d_out, int out_size) {
    const float* x       = (const float*)d_in[0];
    const float* ori     = (const float*)d_in[1];
    const float* bn_a_g  = (const float*)d_in[2];
    const float* bn_a_b  = (const float*)d_in[3];
    const float* tconv_w = (const float*)d_in[4];
    const float* tconv_b = (const float*)d_in[5];
    const float* bn_p_g  = (const float*)d_in[6];
    const float* bn_p_b  = (const float*)d_in[7];
    const float* proj_w  = (const float*)d_in[8];
    const float* proj_b  = (const float*)d_in[9];
    const float* pos_w   = (const float*)d_in[10];
    const float* pos_b   = (const float*)d_in[11];
    const float* bn_t_g  = (const float*)d_in[12];
    const float* bn_t_b  = (const float*)d_in[13];
    const float* dw_w    = (const float*)d_in[14];
    const float* dw_b    = (const float*)d_in[15];
    const float* pw_w    = (const float*)d_in[16];
    const float* pw_b    = (const float*)d_in[17];
    const float* bn_c_g  = (const float*)d_in[18];
    const float* bn_c_b  = (const float*)d_in[19];
    const float* fc1_w   = (const float*)d_in[20];
    const float* fc1_b   = (const float*)d_in[21];
    const float* fc2_w   = (const float*)d_in[22];
    const float* fc2_b   = (const float*)d_in[23];

    float* out  = (float*)d_out;
    float* outp = out + out_size / 2;

    float *p_xp, *p_kpT;
    __nv_bfloat16 *p_colh, *p_coll, *p_pwh, *p_pwl, *p_kmh, *p_kml;
    __nv_bfloat16 *p_f1h, *p_f1l, *p_f2h, *p_f2l, *p_hh, *p_hl;
    cudaGetSymbolAddress((void**)&p_xp,    g_xp);
    cudaGetSymbolAddress((void**)&p_kpT,   g_kpT);
    cudaGetSymbolAddress((void**)&p_colh,  g_colh);
    cudaGetSymbolAddress((void**)&p_coll,  g_coll);
    cudaGetSymbolAddress((void**)&p_pwh,   g_pwh);
    cudaGetSymbolAddress((void**)&p_pwl,   g_pwl);
    cudaGetSymbolAddress((void**)&p_kmh,   g_kmh);
    cudaGetSymbolAddress((void**)&p_kml,   g_kml);
    cudaGetSymbolAddress((void**)&p_f1h,   g_f1h);
    cudaGetSymbolAddress((void**)&p_f1l,   g_f1l);
    cudaGetSymbolAddress((void**)&p_f2h,   g_f2h);
    cudaGetSymbolAddress((void**)&p_f2l,   g_f2l);
    cudaGetSymbolAddress((void**)&p_hh,    g_hh);
    cudaGetSymbolAddress((void**)&p_hl,    g_hl);

    const int SMEM_HG = 3 * STGB;  // 73728 B (covers 66048 B epilogue buffer)
    cudaFuncSetAttribute(k_hgemm, cudaFuncAttributeMaxDynamicSharedMemorySize, SMEM_HG);

    k_zero<<<1, 768>>>();
    k_bn_a<<<CIN, 256>>>(x, bn_a_g, bn_a_b);
    k_tconv<<<196, 256>>>(x, tconv_w, tconv_b, ori);
    k_bnv_part<<<dim3(3, 32), 256>>>();
    k_bnv_final<<<3, 32>>>(bn_p_g, bn_p_b);
    k_im2col<<<(int)(((size_t)MPROJ*576 + 255)/256), 256>>>();
    k_cvtpad<<<(int)(((size_t)CDIM*KPROJ + 255)/256), 256>>>(proj_w, p_pwh, p_pwl, CDIM, KPROJ, KPROJ);
    // proj: M=22472, N=768, K=2304 -> xp fp32
    k_hgemm<<<dim3(6, 176), 256, SMEM_HG>>>(p_colh, p_coll, KPROJ, p_pwh, p_pwl, KPROJ,
                                            proj_b, p_xp, nullptr, nullptr,
                                            MPROJ, CDIM, KPROJ, CDIM, 0);
    k_pos<<<dim3(HH, TD, NB), 768>>>(pos_w, pos_b);
    k_bnstat<<<88, 256>>>();
    k_bnfin<<<1, 768>>>(bn_t_g, bn_t_b, bn_c_g, bn_c_b);
    k_dw<<<dim3(HH, NB), 768>>>(dw_w, dw_b);
    k_sel<<<dim3(HWD, NB), 256>>>(pw_w, pw_b);
    k_selmax<<<dim3(NTOK, NB), 256>>>();
    k_temgather<<<dim3(NTOK, NB), 256>>>(out, outp);
    k_kmat<<<dim3((KFP+127)/128, CDIM, BT3), 128>>>();
    k_cvtpad<<<(int)(((size_t)KF*KFP  + 255)/256), 256>>>(fc1_w, p_f1h, p_f1l, KF,  KF, KFP);
    k_cvtpad<<<(int)(((size_t)HWD*KFP + 255)/256), 256>>>(fc2_w, p_f2h, p_f2l, HWD, KF, KFP);
    // fc1: M=4608, N=2841, K=2880, gelu -> h hi/lo
    k_hgemm<<<dim3(23, 36), 256, SMEM_HG>>>(p_kmh, p_kml, KFP, p_f1h, p_f1l, KFP,
                                            fc1_b, nullptr, p_hh, p_hl,
                                            MROWS, KF, KFP, KFP, 1);
    // fc2: M=4608, N=2809, K=2880 -> kpT fp32 transposed
    k_hgemm<<<dim3(22, 36), 256, SMEM_HG>>>(p_hh, p_hl, KFP, p_f2h, p_f2l, KFP,
                                            fc2_b, p_kpT, nullptr, nullptr,
                                            MROWS, HWD, KFP, 0, 2);
    // score: dedicated 32x128 tile GEMM, z=6
    k_score<<<dim3(22, BT3), 256>>>();
    k_scoremax<<<dim3(NTOK, BT3), 256>>>();
    k_route<<<dim3(NTOK, BT3), 256>>>(out, outp);
}

// round 16
// speedup vs baseline: 1.0009x; 1.0009x over previous
#include <cuda_runtime.h>
#include <cuda_bf16.h>
#include <math.h>
#include <stdint.h>

#define NB     2
#define CIN    320
#define TT0    4
#define HW0    196
#define VPLANE 50176
#define VF     8
#define CDIM   768
#define TD     4
#define HH     53
#define HWD    2809
#define MPROJ  22472          // NB*TD*HWD
#define KPROJ  2304
#define NTOK   32
#define KF     2841
#define KFP    2880           // padded to multiple of 16
#define BT3    6
#define MROWS  4608           // BT3*CDIM
#define EPSBN  1e-5

// ---------------- static scratch ----------------
__device__ float  g_scaleA[CIN], g_shiftA[CIN];
__device__ float  g_v[(size_t)NB*3*VF*VPLANE];
__device__ double g_redV[3*32*2];
__device__ float  g_scaleP[3], g_shiftP[3];
__device__ float  g_xp [(size_t)MPROJ*CDIM];
__device__ float  g_pos[(size_t)MPROJ*CDIM];
__device__ double g_sumT[CDIM], g_sumsqT[CDIM], g_sumC[CDIM], g_sumsqC[CDIM];
__device__ float  g_scaleT[CDIM], g_shiftT[CDIM];
__device__ float  g_scaleC[CDIM], g_shiftC[CDIM];
__device__ float  g_d [(size_t)NB*HWD*CDIM];
__device__ float  g_sel[(size_t)NB*HWD*NTOK];
__device__ float  g_selmax[NB*NTOK];
__device__ float  g_tem [NB*NTOK*CDIM];
__device__ float  g_kpT [(size_t)BT3*HWD*CDIM];
__device__ float  g_score[(size_t)BT3*NTOK*HWD];
__device__ float  g_smax[BT3*NTOK];
// bf16 hi/lo operand buffers
__device__ __nv_bfloat16 g_colh[(size_t)MPROJ*KPROJ], g_coll[(size_t)MPROJ*KPROJ];
__device__ __nv_bfloat16 g_pwh[(size_t)CDIM*KPROJ],   g_pwl[(size_t)CDIM*KPROJ];
__device__ __nv_bfloat16 g_kmh[(size_t)MROWS*KFP],    g_kml[(size_t)MROWS*KFP];
__device__ __nv_bfloat16 g_f1h[(size_t)KF*KFP],       g_f1l[(size_t)KF*KFP];
__device__ __nv_bfloat16 g_f2h[(size_t)HWD*KFP],      g_f2l[(size_t)HWD*KFP];
__device__ __nv_bfloat16 g_hh [(size_t)MROWS*KFP],    g_hl [(size_t)MROWS*KFP];

// ---------------- helpers ----------------
__device__ __forceinline__ uint32_t smem_u32(const void* p) {
    uint32_t a;
    asm("{ .reg .u64 t; cvta.to.shared.u64 t, %1; cvt.u32.u64 %0, t; }" : "=r"(a) : "l"(p));
    return a;
}
__device__ __forceinline__ void ldsm4(uint32_t* r, uint32_t addr) {
    asm volatile("ldmatrix.sync.aligned.m8n8.x4.shared.b16 {%0,%1,%2,%3}, [%4];"
        : "=r"(r[0]), "=r"(r[1]), "=r"(r[2]), "=r"(r[3]) : "r"(addr));
}
__device__ __forceinline__ void mma16816(float* c, const uint32_t* a, uint32_t b0, uint32_t b1) {
    asm volatile("mma.sync.aligned.m16n8k16.row.col.f32.bf16.bf16.f32 "
        "{%0,%1,%2,%3},{%4,%5,%6,%7},{%8,%9},{%0,%1,%2,%3};"
        : "+f"(c[0]), "+f"(c[1]), "+f"(c[2]), "+f"(c[3])
        : "r"(a[0]), "r"(a[1]), "r"(a[2]), "r"(a[3]), "r"(b0), "r"(b1));
}
__device__ __forceinline__ void cpa16(uint32_t dst, const void* src, int srcsize) {
    asm volatile("cp.async.cg.shared.global [%0], [%1], 16, %2;"
        :: "r"(dst), "l"(src), "r"(srcsize) : "memory");
}
#define CP_COMMIT() asm volatile("cp.async.commit_group;" ::: "memory")
#define CP_WAIT1()  asm volatile("cp.async.wait_group 1;" ::: "memory")
#define CP_WAIT0()  asm volatile("cp.async.wait_group 0;" ::: "memory")

__device__ __forceinline__ void split_bf16(float x, __nv_bfloat16 &h, __nv_bfloat16 &l) {
    h = __float2bfloat16(x);
    l = __float2bfloat16(x - __bfloat162float(h));
}

// ================= HMMA bf16x3 GEMM (128x128 block, 64x32 warp tile, cp.async x3) =================
// EXACT copy of the 3931.6us R10 kernel.
#define LDSE   24                    // smem row stride (bf16) = 48 B
#define MATB   (128*48)              // 6144 B per matrix tile
#define STGB   (4*MATB)              // 24576 B per stage
__global__ __launch_bounds__(256, 2) void k_hgemm(
    const __nv_bfloat16* __restrict__ Ah, const __nv_bfloat16* __restrict__ Al, int lda,
    const __nv_bfloat16* __restrict__ Bh, const __nv_bfloat16* __restrict__ Bl, int ldb,
    const float* __restrict__ bias, float* __restrict__ Cf,
    __nv_bfloat16* __restrict__ Oh, __nv_bfloat16* __restrict__ Ol,
    int M, int N, int K, int ldc, int mode)
{
    extern __shared__ char smem[];
    const uint32_t sbase = smem_u32(smem);
    const int tid = threadIdx.x;
    const int wid = tid >> 5, lane = tid & 31;
    const int m0 = blockIdx.y * 128, n0 = blockIdx.x * 128;
    const int wm = wid & 1, wn = wid >> 1;   // warp tile 64(m) x 32(n)

    // ---- loaders: mat = tid>>6 (0:Ah 1:Al 2:Bh 3:Bl), 2 rows each ----
    const int mat = tid >> 6;
    const int rr  = (tid & 63) << 1;
    const __nv_bfloat16* src; int ld, base, lim;
    if      (mat == 0) { src = Ah; ld = lda; base = m0; lim = M; }
    else if (mat == 1) { src = Al; ld = lda; base = m0; lim = M; }
    else if (mat == 2) { src = Bh; ld = ldb; base = n0; lim = N; }
    else               { src = Bl; ld = ldb; base = n0; lim = N; }
    const int sz0 = ((base + rr)     < lim) ? 16 : 0;
    const int sz1 = ((base + rr + 1) < lim) ? 16 : 0;
    const char* p0 = (const char*)(src + (size_t)(sz0 ? base + rr     : 0) * ld);
    const char* p1 = (const char*)(src + (size_t)(sz1 ? base + rr + 1 : 0) * ld);
    const uint32_t d0 = sbase + mat * MATB + rr * 48;
    const uint32_t d1 = d0 + 48;

    // ---- fragment smem offsets ----
    const uint32_t afo = (uint32_t)(((wm * 64 + (lane & 15)) * LDSE + (lane >> 4) * 8) * 2);
    const uint32_t bfo = (uint32_t)(((wn * 32 + (lane & 15)) * LDSE + (lane >> 4) * 8) * 2);

    float acc[4][4][4];
    #pragma unroll
    for (int i = 0; i < 4; i++)
        #pragma unroll
        for (int j = 0; j < 4; j++)
            #pragma unroll
            for (int q = 0; q < 4; q++) acc[i][j][q] = 0.f;

    const int KT = K >> 4;

    // prologue: stages 0 and 1
    cpa16(d0, p0, sz0); cpa16(d0 + 16, p0 + 16, sz0);
    cpa16(d1, p1, sz1); cpa16(d1 + 16, p1 + 16, sz1);
    CP_COMMIT();
    if (KT > 1) {
        cpa16(d0 + STGB, p0 + 32, sz0); cpa16(d0 + STGB + 16, p0 + 48, sz0);
        cpa16(d1 + STGB, p1 + 32, sz1); cpa16(d1 + STGB + 16, p1 + 48, sz1);
    }
    CP_COMMIT();

    int buf = 0;
    for (int kt = 0; kt < KT; kt++) {
        CP_WAIT1();
        __syncthreads();
        const uint32_t st = sbase + buf * STGB;
        uint32_t bh[2][4], bl[2][4];
        #pragma unroll
        for (int t = 0; t < 2; t++) {
            ldsm4(bh[t], st + 2*MATB + bfo + t * (16 * 48));
            ldsm4(bl[t], st + 3*MATB + bfo + t * (16 * 48));
        }
        #pragma unroll
        for (int i = 0; i < 4; i++) {
            uint32_t ah4[4], al4[4];
            ldsm4(ah4, st + afo + i * (16 * 48));
            ldsm4(al4, st + MATB + afo + i * (16 * 48));
            #pragma unroll
            for (int j = 0; j < 4; j++) {
                const int t = j >> 1, o = j & 1;
                mma16816(acc[i][j], ah4, bh[t][o], bh[t][2 + o]);
                mma16816(acc[i][j], ah4, bl[t][o], bl[t][2 + o]);
                mma16816(acc[i][j], al4, bh[t][o], bh[t][2 + o]);
            }
        }
        if (kt + 2 < KT) {
            const int nb = (buf + 2) % 3;
            const size_t ko = (size_t)(kt + 2) * 32;
            const uint32_t w0 = d0 + nb * STGB, w1 = d1 + nb * STGB;
            cpa16(w0, p0 + ko, sz0); cpa16(w0 + 16, p0 + ko + 16, sz0);
            cpa16(w1, p1 + ko, sz1); cpa16(w1 + 16, p1 + ko + 16, sz1);
        }
        CP_COMMIT();
        buf = (buf + 1) % 3;
    }
    CP_WAIT0();
    __syncthreads();

    // ---- epilogue: stage acc -> smf[128][129] ----
    float* smf = (float*)smem;
    #pragma unroll
    for (int i = 0; i < 4; i++) {
        const int mr = wm * 64 + i * 16 + (lane >> 2);
        #pragma unroll
        for (int j = 0; j < 4; j++) {
            const int nc = wn * 32 + j * 8 + (lane & 3) * 2;
            smf[mr * 129 + nc]           = acc[i][j][0];
            smf[mr * 129 + nc + 1]       = acc[i][j][1];
            smf[(mr + 8) * 129 + nc]     = acc[i][j][2];
            smf[(mr + 8) * 129 + nc + 1] = acc[i][j][3];
        }
    }
    __syncthreads();

    if (mode == 0) {
        for (int idx = tid; idx < 128 * 128; idx += 256) {
            const int mm = idx >> 7, nn = idx & 127;
            const int m = m0 + mm, n = n0 + nn;
            if (m < M && n < N)
                Cf[(size_t)m * ldc + n] = smf[mm * 129 + nn] + (bias ? bias[n] : 0.f);
        }
    } else if (mode == 1) {
        for (int idx = tid; idx < 128 * 128; idx += 256) {
            const int mm = idx >> 7, nn = idx & 127;
            const int m = m0 + mm, n = n0 + nn;
            if (m < M && n < ldc) {
                float v = 0.f;
                if (n < N) {
                    v = smf[mm * 129 + nn] + bias[n];
                    v = 0.5f * v * (1.f + erff(v * 0.70710678118654752f));
                }
                __nv_bfloat16 h, l; split_bf16(v, h, l);
                Oh[(size_t)m * ldc + n] = h;
                Ol[(size_t)m * ldc + n] = l;
            }
        }
    } else {
        const int z2 = m0 / CDIM, cbase = m0 % CDIM;
        for (int idx = tid; idx < 128 * 128; idx += 256) {
            const int mm = idx & 127, jn = idx >> 7;
            const int n = n0 + jn;
            if (n < N)
                Cf[((size_t)z2 * HWD + n) * CDIM + cbase + mm] =
                    smf[mm * 129 + jn] + bias[n];
        }
    }
}

// ---------------- dedicated score GEMM ----------------
__global__ __launch_bounds__(256) void k_score() {
    const int z = blockIdx.y, hw0 = blockIdx.x * 128;
    const int b = z / 3;
    const int tid = threadIdx.x;
    const int hwl = tid & 127, ng = tid >> 7;
    __shared__ float tems[32][64];
    __shared__ float kps[128][65];
    float acc[16];
    #pragma unroll
    for (int i = 0; i < 16; i++) acc[i] = 0.f;
    const int hw = hw0 + hwl;

    for (int k0 = 0; k0 < CDIM; k0 += 64) {
        __syncthreads();
        for (int i = tid; i < 32 * 64; i += 256) {
            int n = i >> 6, c = i & 63;
            tems[n][c] = g_tem[((size_t)b * NTOK + n) * CDIM + k0 + c];
        }
        for (int i = tid; i < 128 * 16; i += 256) {
            int r = i >> 4, c4 = (i & 15) << 2;
            float4 v = (hw0 + r < HWD)
                ? *(const float4*)&g_kpT[((size_t)z * HWD + hw0 + r) * CDIM + k0 + c4]
                : make_float4(0.f, 0.f, 0.f, 0.f);
            kps[r][c4] = v.x; kps[r][c4+1] = v.y; kps[r][c4+2] = v.z; kps[r][c4+3] = v.w;
        }
        __syncthreads();
        #pragma unroll 16
        for (int kk = 0; kk < 64; kk++) {
            float kv = kps[hwl][kk];
            #pragma unroll
            for (int nn = 0; nn < 16; nn++)
                acc[nn] = fmaf(tems[ng * 16 + nn][kk], kv, acc[nn]);
        }
    }
    if (hw < HWD) {
        #pragma unroll
        for (int nn = 0; nn < 16; nn++)
            g_score[((size_t)z * NTOK + ng * 16 + nn) * HWD + hw] = acc[nn];
    }
}

// ---------------- zero accumulators ----------------
__global__ void k_zero() {
    int i = threadIdx.x;
    if (i < CDIM) { g_sumT[i]=0.0; g_sumsqT[i]=0.0; g_sumC[i]=0.0; g_sumsqC[i]=0.0; }
}

// ---------------- BN over x (320 ch) ----------------
__global__ void k_bn_a(const float* __restrict__ x, const float* __restrict__ g,
                       const float* __restrict__ b) {
    int c = blockIdx.x;
    double s = 0.0, s2 = 0.0;
    for (int i = threadIdx.x; i < NB*TT0*HW0; i += blockDim.x) {
        int bb = i / (TT0*HW0), r = i % (TT0*HW0);
        float v = x[((size_t)(bb*CIN + c))*(TT0*HW0) + r];
        s += v; s2 += (double)v * v;
    }
    __shared__ double sh[256], sh2[256];
    sh[threadIdx.x] = s; sh2[threadIdx.x] = s2;
    __syncthreads();
    for (int o = 128; o > 0; o >>= 1) {
        if (threadIdx.x < o) { sh[threadIdx.x] += sh[threadIdx.x+o]; sh2[threadIdx.x] += sh2[threadIdx.x+o]; }
        __syncthreads();
    }
    if (threadIdx.x == 0) {
        double n = (double)(NB*TT0*HW0);
        double mean = sh[0]/n, var = sh2[0]/n - mean*mean;
        float sc = (float)((double)g[c] / sqrt(var + EPSBN));
        g_scaleA[c] = sc;
        g_shiftA[c] = b[c] - (float)mean * sc;
    }
}

// ---------------- tconv + relu6 + residual -> g_v (8 positions/block) ----------------
__global__ __launch_bounds__(256) void k_tconv(
    const float* __restrict__ x, const float* __restrict__ tw,
    const float* __restrict__ tb, const float* __restrict__ ori) {
    __shared__ float xs[8][CIN];
    int tid = threadIdx.x;
    for (int idx = tid; idx < 8*CIN; idx += 256) {
        int p = idx / CIN, i = idx % CIN;
        int lin = blockIdx.x * 8 + p;
        int w = lin % 14, h = (lin/14) % 14, t = (lin/196) % TT0, bb = lin/(196*TT0);
        xs[p][i] = x[((size_t)(bb*CIN+i)*TT0 + t)*HW0 + h*14 + w] * g_scaleA[i] + g_shiftA[i];
    }
    __syncthreads();
    for (int jj = tid; jj < 1536; jj += 256) {
        float a[8];
        #pragma unroll
        for (int p = 0; p < 8; p++) a[p] = 0.f;
        const float* wp = tw + jj;
        #pragma unroll 4
        for (int i = 0; i < CIN; i++) {
            float wv = *wp; wp += 1536;
            #pragma unroll
            for (int p = 0; p < 8; p++) a[p] = fmaf(xs[p][i], wv, a[p]);
        }
        int o = jj >> 9, rem = jj & 511;
        int k = rem >> 8, p = (rem >> 4) & 15, q = rem & 15;
        float bias = tb[o];
        #pragma unroll
        for (int pp = 0; pp < 8; pp++) {
            int lin = blockIdx.x * 8 + pp;
            int w = lin % 14, h = (lin/14) % 14, t = (lin/196) % TT0, bb = lin/(196*TT0);
            float val = fminf(fmaxf(a[pp] + bias, 0.f), 6.f);
            size_t oidx = ((size_t)(bb*3+o)*VF + (2*t+k))*VPLANE + (16*h+p)*224 + (16*w+q);
            g_v[oidx] = val + ori[oidx];
        }
    }
}

// ---------------- BN stats of v (3 ch) ----------------
__global__ void k_bnv_part() {
    int ch = blockIdx.x, part = blockIdx.y;
    const int per = (NB*VF*VPLANE) / 32;
    double s = 0.0, s2 = 0.0;
    int base = part * per;
    for (int i = threadIdx.x; i < per; i += blockDim.x) {
        int gi = base + i;
        int b = gi / (VF*VPLANE), r = gi % (VF*VPLANE);
        float v = g_v[((size_t)(b*3+ch))*VF*VPLANE + r];
        s += v; s2 += (double)v * v;
    }
    __shared__ double sh[256], sh2[256];
    sh[threadIdx.x] = s; sh2[threadIdx.x] = s2;
    __syncthreads();
    for (int o = 128; o > 0; o >>= 1) {
        if (threadIdx.x < o) { sh[threadIdx.x] += sh[threadIdx.x+o]; sh2[threadIdx.x] += sh2[threadIdx.x+o]; }
        __syncthreads();
    }
    if (threadIdx.x == 0) { g_redV[(ch*32+part)*2] = sh[0]; g_redV[(ch*32+part)*2+1] = sh2[0]; }
}
__global__ void k_bnv_final(const float* __restrict__ g, const float* __restrict__ b) {
    int ch = blockIdx.x;
    double s  = g_redV[(ch*32 + threadIdx.x)*2];
    double s2 = g_redV[(ch*32 + threadIdx.x)*2 + 1];
    for (int o = 16; o > 0; o >>= 1) {
        s  += __shfl_down_sync(0xffffffffu, s,  o);
        s2 += __shfl_down_sync(0xffffffffu, s2, o);
    }
    if (threadIdx.x == 0) {
        double n = (double)(NB*VF*VPLANE);
        double mean = s/n, var = s2/n - mean*mean;
        float sc = (float)((double)g[ch] / sqrt(var + EPSBN));
        g_scaleP[ch] = sc;
        g_shiftP[ch] = b[ch] - (float)mean * sc;
    }
}

// ---------------- im2col -> bf16 hi/lo (BN folded, zero t-pad) ----------------
__global__ void k_im2col() {
    size_t idx = (size_t)blockIdx.x * 256 + threadIdx.x;
    if (idx >= (size_t)MPROJ * 576) return;
    int m  = (int)(idx / 576);
    int k4 = (int)(idx % 576) * 4;
    int c  = k4 / 768;
    int kt = (k4 % 768) / 256;
    int p  = (k4 % 256) / 16;
    int q  = k4 % 16;
    int w = m % HH, h = (m/HH) % HH, t = (m/HWD) % TD, b = m / (TD*HWD);
    int it = 2*t + kt - 1;
    float4 o;
    if (it < 0 || it > 7) {
        o = make_float4(0.f, 0.f, 0.f, 0.f);
    } else {
        const float* src = g_v + ((size_t)(b*3+c)*VF + it)*VPLANE + (4*h+p)*224 + (4*w+q);
        float4 v = *(const float4*)src;
        float sc = g_scaleP[c], sh = g_shiftP[c];
        o = make_float4(v.x*sc+sh, v.y*sc+sh, v.z*sc+sh, v.w*sc+sh);
    }
    __nv_bfloat16 h0,h1,h2,h3,l0,l1,l2,l3;
    split_bf16(o.x,h0,l0); split_bf16(o.y,h1,l1); split_bf16(o.z,h2,l2); split_bf16(o.w,h3,l3);
    uint2 ph, pl;
    ph.x = (uint32_t)__bfloat16_as_ushort(h0) | ((uint32_t)__bfloat16_as_ushort(h1) << 16);
    ph.y = (uint32_t)__bfloat16_as_ushort(h2) | ((uint32_t)__bfloat16_as_ushort(h3) << 16);
    pl.x = (uint32_t)__bfloat16_as_ushort(l0) | ((uint32_t)__bfloat16_as_ushort(l1) << 16);
    pl.y = (uint32_t)__bfloat16_as_ushort(l2) | ((uint32_t)__bfloat16_as_ushort(l3) << 16);
    *(uint2*)(g_colh + (size_t)m*KPROJ + k4) = ph;
    *(uint2*)(g_coll + (size_t)m*KPROJ + k4) = pl;
}

// ---------------- fp32 -> bf16 hi/lo weight convert with K padding ----------------
__global__ void k_cvtpad(const float* __restrict__ src, __nv_bfloat16* __restrict__ dh,
                         __nv_bfloat16* __restrict__ dl, int rows, int kin, int kout) {
    size_t idx = (size_t)blockIdx.x * 256 + threadIdx.x;
    if (idx >= (size_t)rows * kout) return;
    int rr = (int)(idx / kout), k = (int)(idx % kout);
    float v = (k < kin) ? src[(size_t)rr * kin + k] : 0.f;
    __nv_bfloat16 h, l; split_bf16(v, h, l);
    dh[idx] = h; dl[idx] = l;
}

// ---------------- pos conv: depthwise 3x3x3 pad 1 on raw xp ----------------
__global__ __launch_bounds__(768) void k_pos(const float* __restrict__ pw,
                                             const float* __restrict__ pb) {
    int h = blockIdx.x, t = blockIdx.y, b = blockIdx.z;
    int c = threadIdx.x;
    float w27[27];
    #pragma unroll
    for (int i = 0; i < 27; i++) w27[i] = pw[c*27 + i];
    float bias = pb[c];
    float prv[9], cur[9], nxt[9];
    #pragma unroll
    for (int j = 0; j < 9; j++) { prv[j] = 0.f; cur[j] = 0.f; }
    #pragma unroll
    for (int j = 0; j < 9; j++) {
        int dt = j/3 - 1, dh = j%3 - 1;
        int tt = t + dt, hh = h + dh;
        cur[j] = (tt >= 0 && tt < TD && hh >= 0 && hh < HH)
                 ? g_xp[(((size_t)(b*TD+tt)*HWD) + hh*HH + 0)*CDIM + c] : 0.f;
    }
    for (int w = 0; w < HH; w++) {
        #pragma unroll
        for (int j = 0; j < 9; j++) {
            int dt = j/3 - 1, dh = j%3 - 1;
            int tt = t + dt, hh = h + dh;
            nxt[j] = (w+1 < HH && tt >= 0 && tt < TD && hh >= 0 && hh < HH)
                     ? g_xp[(((size_t)(b*TD+tt)*HWD) + hh*HH + (w+1))*CDIM + c] : 0.f;
        }
        float acc = bias;
        #pragma unroll
        for (int j = 0; j < 9; j++) {
            acc = fmaf(prv[j], w27[j*3+0], acc);
            acc = fmaf(cur[j], w27[j*3+1], acc);
            acc = fmaf(nxt[j], w27[j*3+2], acc);
        }
        g_pos[(((size_t)(b*TD+t)*HWD) + h*HH + w)*CDIM + c] = acc;
        #pragma unroll
        for (int j = 0; j < 9; j++) { prv[j] = cur[j]; cur[j] = nxt[j]; }
    }
}

// ---------------- merged BN stats ----------------
__global__ void k_bnstat() {
    int tid = threadIdx.x;
    double sc_[3] = {0,0,0}, sc2[3] = {0,0,0};
    double st_[3] = {0,0,0}, st2[3] = {0,0,0};
    int r0 = blockIdx.x * 256;
    for (int i = 0; i < 256; i++) {
        int r = r0 + i;
        if (r >= MPROJ) break;
        bool isT0 = ((r / HWD) % TD) == 0;
        size_t base = (size_t)r * CDIM;
        #pragma unroll
        for (int k = 0; k < 3; k++) {
            float v = g_xp[base + tid + 256*k];
            double dv = (double)v;
            sc_[k] += dv; sc2[k] += dv * dv;
            if (isT0) { st_[k] += dv; st2[k] += dv * dv; }
        }
    }
    #pragma unroll
    for (int k = 0; k < 3; k++) {
        atomicAdd(&g_sumC[tid + 256*k],   sc_[k]);
        atomicAdd(&g_sumsqC[tid + 256*k], sc2[k]);
        atomicAdd(&g_sumT[tid + 256*k],   st_[k]);
        atomicAdd(&g_sumsqT[tid + 256*k], st2[k]);
    }
}
__global__ void k_bnfin(const float* gt, const float* bt,
                        const float* gc, const float* bc) {
    int c = threadIdx.x;
    {
        double n = (double)(NB*HWD);
        double mean = g_sumT[c]/n, var = g_sumsqT[c]/n - mean*mean;
        float sc = (float)((double)gt[c] / sqrt(var + EPSBN));
        g_scaleT[c] = sc; g_shiftT[c] = bt[c] - (float)mean * sc;
    }
    {
        double n = (double)MPROJ;
        double mean = g_sumC[c]/n, var = g_sumsqC[c]/n - mean*mean;
        float sc = (float)((double)gc[c] / sqrt(var + EPSBN));
        g_scaleC[c] = sc; g_shiftC[c] = bc[c] - (float)mean * sc;
    }
}

// ---------------- token-selector depthwise 3x3 + hardswish (BN_t inline) ----------------
__global__ __launch_bounds__(768) void k_dw(const float* __restrict__ dw,
                                            const float* __restrict__ db) {
    int h = blockIdx.x, b = blockIdx.y;
    int c = threadIdx.x;
    float w9[9];
    #pragma unroll
    for (int i = 0; i < 9; i++) w9[i] = dw[c*9 + i];
    float bias = db[c];
    const float scT = g_scaleT[c], shT = g_shiftT[c];
    const size_t xb0 = (size_t)(b*TD) * HWD;   // frame-0 base row of xp
    float prv[3], cur[3], nxt[3];
    #pragma unroll
    for (int j = 0; j < 3; j++) prv[j] = 0.f;
    #pragma unroll
    for (int j = 0; j < 3; j++) {
        int hh = h + j - 1;
        cur[j] = (hh >= 0 && hh < HH)
                 ? fmaf(g_xp[(xb0 + hh*HH + 0)*CDIM + c], scT, shT) : 0.f;
    }
    for (int w = 0; w < HH; w++) {
        #pragma unroll
        for (int j = 0; j < 3; j++) {
            int hh = h + j - 1;
            nxt[j] = (w+1 < HH && hh >= 0 && hh < HH)
                     ? fmaf(g_xp[(xb0 + hh*HH + (w+1))*CDIM + c], scT, shT) : 0.f;
        }
        float acc = bias;
        #pragma unroll
        for (int j = 0; j < 3; j++) {
            acc = fmaf(prv[j], w9[j*3+0], acc);
            acc = fmaf(cur[j], w9[j*3+1], acc);
            acc = fmaf(nxt[j], w9[j*3+2], acc);
        }
        float hs = acc * fminf(fmaxf(acc + 3.f, 0.f), 6.f) * (1.f/6.f);
        g_d[((size_t)b*HWD + h*HH + w)*CDIM + c] = hs;
        #pragma unroll
        for (int j = 0; j < 3; j++) { prv[j] = cur[j]; cur[j] = nxt[j]; }
    }
}

// ---------------- sel = pw(d) ----------------
__global__ void k_sel(const float* __restrict__ pww, const float* __restrict__ pwb) {
    int hw = blockIdx.x, b = blockIdx.y;
    __shared__ float ds[CDIM];
    for (int c = threadIdx.x; c < CDIM; c += 256)
        ds[c] = g_d[((size_t)b*HWD + hw)*CDIM + c];
    __syncthreads();
    int n = threadIdx.x >> 3, sub = threadIdx.x & 7;
    float acc = 0.f;
    for (int c = sub; c < CDIM; c += 8)
        acc = fmaf(ds[c], pww[n*CDIM + c], acc);
    acc += __shfl_xor_sync(0xffffffffu, acc, 1);
    acc += __shfl_xor_sync(0xffffffffu, acc, 2);
    acc += __shfl_xor_sync(0xffffffffu, acc, 4);
    if (sub == 0) g_sel[((size_t)b*HWD + hw)*NTOK + n] = acc + pwb[n];
}

__global__ void k_selmax() {
    int n = blockIdx.x, b = blockIdx.y;
    float m = -3.4e38f;
    for (int hw = threadIdx.x; hw < HWD; hw += 256)
        m = fmaxf(m, g_sel[((size_t)b*HWD + hw)*NTOK + n]);
    __shared__ float sh[256];
    sh[threadIdx.x] = m;
    __syncthreads();
    for (int o = 128; o > 0; o >>= 1) {
        if (threadIdx.x < o) sh[threadIdx.x] = fmaxf(sh[threadIdx.x], sh[threadIdx.x+o]);
        __syncthreads();
    }
    if (threadIdx.x == 0) g_selmax[b*NTOK + n] = sh[0];
}

// ---------------- tem gather (BN_t inline for feat) ----------------
__global__ void k_temgather(float* __restrict__ out, float* __restrict__ outp) {
    int n = blockIdx.x, b = blockIdx.y;
    __shared__ unsigned char flag[HWD];
    float mx = g_selmax[b*NTOK + n];
    for (int hw = threadIdx.x; hw < HWD; hw += 256)
        flag[hw] = (g_sel[((size_t)b*HWD + hw)*NTOK + n] == mx) ? 1 : 0;
    __syncthreads();
    int c0 = threadIdx.x, c1 = threadIdx.x + 256, c2 = threadIdx.x + 512;
    const float sc0 = g_scaleT[c0], sh0 = g_shiftT[c0];
    const float sc1 = g_scaleT[c1], sh1 = g_shiftT[c1];
    const float sc2 = g_scaleT[c2], sh2 = g_shiftT[c2];
    float a0=0,a1=0,a2=0, p0=0,p1=0,p2=0;
    for (int hw = 0; hw < HWD; hw++) {
        if (flag[hw]) {
            size_t pb = ((size_t)(b*TD)*HWD + hw)*CDIM;
            a0 += fmaf(g_xp[pb+c0], sc0, sh0);
            a1 += fmaf(g_xp[pb+c1], sc1, sh1);
            a2 += fmaf(g_xp[pb+c2], sc2, sh2);
            p0 += g_pos[pb+c0]; p1 += g_pos[pb+c1]; p2 += g_pos[pb+c2];
        }
    }
    size_t tb = ((size_t)b*NTOK + n)*CDIM;
    g_tem[tb+c0]=a0; g_tem[tb+c1]=a1; g_tem[tb+c2]=a2;
    size_t ob = ((size_t)(b*TD + 0)*NTOK + n)*CDIM;
    out[ob+c0]=a0; out[ob+c1]=a1; out[ob+c2]=a2;
    outp[ob+c0]=p0; outp[ob+c1]=p1; outp[ob+c2]=p2;
}

// ---------------- build kmat hi/lo [z*768+c][j], ld=KFP ----------------
__global__ void k_kmat() {
    int j = blockIdx.x * 128 + threadIdx.x;
    if (j >= KFP) return;
    int c = blockIdx.y, z = blockIdx.z;
    int b = z / 3, t = z % 3;
    float v;
    if (j < NTOK)      v = g_tem[((size_t)b*NTOK + j)*CDIM + c];
    else if (j < KF)   v = g_xp[((size_t)(b*TD + t + 1)*HWD + (j - NTOK))*CDIM + c]
                           * g_scaleC[c] + g_shiftC[c];
    else               v = 0.f;
    __nv_bfloat16 h, l; split_bf16(v, h, l);
    size_t o = ((size_t)z*CDIM + c)*KFP + j;
    g_kmh[o] = h; g_kml[o] = l;
}

// ---------------- score max ----------------
__global__ void k_scoremax() {
    int n = blockIdx.x, z = blockIdx.y;
    float m = -3.4e38f;
    for (int hw = threadIdx.x; hw < HWD; hw += 256)
        m = fmaxf(m, g_score[((size_t)z*NTOK + n)*HWD + hw]);
    __shared__ float sh[256];
    sh[threadIdx.x] = m;
    __syncthreads();
    for (int o = 128; o > 0; o >>= 1) {
        if (threadIdx.x < o) sh[threadIdx.x] = fmaxf(sh[threadIdx.x], sh[threadIdx.x+o]);
        __syncthreads();
    }
    if (threadIdx.x == 0) g_smax[z*NTOK + n] = sh[0];
}

// ---------------- route gather -> out frames 1..3 ----------------
__global__ void k_route(float* __restrict__ out, float* __restrict__ outp) {
    int n = blockIdx.x, z = blockIdx.y;
    int b = z / 3, t = z % 3;
    __shared__ unsigned char flag[HWD];
    float mx = g_smax[z*NTOK + n];
    for (int hw = threadIdx.x; hw < HWD; hw += 256)
        flag[hw] = (g_score[((size_t)z*NTOK + n)*HWD + hw] == mx) ? 1 : 0;
    __syncthreads();
    int c0 = threadIdx.x, c1 = threadIdx.x + 256, c2 = threadIdx.x + 512;
    float s0=0,s1=0,s2=0, p0=0,p1=0,p2=0;
    int cnt = 0;
    for (int hw = 0; hw < HWD; hw++) {
        if (flag[hw]) {
            size_t xb = ((size_t)(b*TD + t + 1)*HWD + hw)*CDIM;
            s0 += g_xp[xb+c0]; s1 += g_xp[xb+c1]; s2 += g_xp[xb+c2];
            p0 += g_pos[xb+c0]; p1 += g_pos[xb+c1]; p2 += g_pos[xb+c2];
            cnt++;
        }
    }
    float fc = (float)cnt;
    size_t ob = ((size_t)(b*TD + t + 1)*NTOK + n)*CDIM;
    out[ob+c0] = g_scaleC[c0]*s0 + fc*g_shiftC[c0];
    out[ob+c1] = g_scaleC[c1]*s1 + fc*g_shiftC[c1];
    out[ob+c2] = g_scaleC[c2]*s2 + fc*g_shiftC[c2];
    outp[ob+c0] = p0; outp[ob+c1] = p1; outp[ob+c2] = p2;
}

// ---------------- launch ----------------
extern "C" void kernel_launch(void* const* d_in, const int* in_sizes, int n_in,
                              void* d_out, int out_size) {
    const float* x       = (const float*)d_in[0];
    const float* ori     = (const float*)d_in[1];
    const float* bn_a_g  = (const float*)d_in[2];
    const float* bn_a_b  = (const float*)d_in[3];
    const float* tconv_w = (const float*)d_in[4];
    const float* tconv_b = (const float*)d_in[5];
    const float* bn_p_g  = (const float*)d_in[6];
    const float* bn_p_b  = (const float*)d_in[7];
    const float* proj_w  = (const float*)d_in[8];
    const float* proj_b  = (const float*)d_in[9];
    const float* pos_w   = (const float*)d_in[10];
    const float* pos_b   = (const float*)d_in[11];
    const float* bn_t_g  = (const float*)d_in[12];
    const float* bn_t_b  = (const float*)d_in[13];
    const float* dw_w    = (const float*)d_in[14];
    const float* dw_b    = (const float*)d_in[15];
    const float* pw_w    = (const float*)d_in[16];
    const float* pw_b    = (const float*)d_in[17];
    const float* bn_c_g  = (const float*)d_in[18];
    const float* bn_c_b  = (const float*)d_in[19];
    const float* fc1_w   = (const float*)d_in[20];
    const float* fc1_b   = (const float*)d_in[21];
    const float* fc2_w   = (const float*)d_in[22];
    const float* fc2_b   = (const float*)d_in[23];

    float* out  = (float*)d_out;
    float* outp = out + out_size / 2;

    float *p_xp, *p_kpT;
    __nv_bfloat16 *p_colh, *p_coll, *p_pwh, *p_pwl, *p_kmh, *p_kml;
    __nv_bfloat16 *p_f1h, *p_f1l, *p_f2h, *p_f2l, *p_hh, *p_hl;
    cudaGetSymbolAddress((void**)&p_xp,    g_xp);
    cudaGetSymbolAddress((void**)&p_kpT,   g_kpT);
    cudaGetSymbolAddress((void**)&p_colh,  g_colh);
    cudaGetSymbolAddress((void**)&p_coll,  g_coll);
    cudaGetSymbolAddress((void**)&p_pwh,   g_pwh);
    cudaGetSymbolAddress((void**)&p_pwl,   g_pwl);
    cudaGetSymbolAddress((void**)&p_kmh,   g_kmh);
    cudaGetSymbolAddress((void**)&p_kml,   g_kml);
    cudaGetSymbolAddress((void**)&p_f1h,   g_f1h);
    cudaGetSymbolAddress((void**)&p_f1l,   g_f1l);
    cudaGetSymbolAddress((void**)&p_f2h,   g_f2h);
    cudaGetSymbolAddress((void**)&p_f2l,   g_f2l);
    cudaGetSymbolAddress((void**)&p_hh,    g_hh);
    cudaGetSymbolAddress((void**)&p_hl,    g_hl);

    const int SMEM_HG = 3 * STGB;  // 73728 B (covers 66048 B epilogue buffer)
    cudaFuncSetAttribute(k_hgemm, cudaFuncAttributeMaxDynamicSharedMemorySize, SMEM_HG);

    k_zero<<<1, 768>>>();
    k_bn_a<<<CIN, 256>>>(x, bn_a_g, bn_a_b);
    k_tconv<<<196, 256>>>(x, tconv_w, tconv_b, ori);
    k_bnv_part<<<dim3(3, 32), 256>>>();
    k_bnv_final<<<3, 32>>>(bn_p_g, bn_p_b);
    k_im2col<<<(int)(((size_t)MPROJ*576 + 255)/256), 256>>>();
    k_cvtpad<<<(int)(((size_t)CDIM*KPROJ + 255)/256), 256>>>(proj_w, p_pwh, p_pwl, CDIM, KPROJ, KPROJ);
    // proj: M=22472, N=768, K=2304 -> xp fp32
    k_hgemm<<<dim3(6, 176), 256, SMEM_HG>>>(p_colh, p_coll, KPROJ, p_pwh, p_pwl, KPROJ,
                                            proj_b, p_xp, nullptr, nullptr,
                                            MPROJ, CDIM, KPROJ, CDIM, 0);
    k_pos<<<dim3(HH, TD, NB), 768>>>(pos_w, pos_b);
    k_bnstat<<<88, 256>>>();
    k_bnfin<<<1, 768>>>(bn_t_g, bn_t_b, bn_c_g, bn_c_b);
    k_dw<<<dim3(HH, NB), 768>>>(dw_w, dw_b);
    k_sel<<<dim3(HWD, NB), 256>>>(pw_w, pw_b);
    k_selmax<<<dim3(NTOK, NB), 256>>>();
    k_temgather<<<dim3(NTOK, NB), 256>>>(out, outp);
    k_kmat<<<dim3((KFP+127)/128, CDIM, BT3), 128>>>();
    k_cvtpad<<<(int)(((size_t)KF*KFP  + 255)/256), 256>>>(fc1_w, p_f1h, p_f1l, KF,  KF, KFP);
    k_cvtpad<<<(int)(((size_t)HWD*KFP + 255)/256), 256>>>(fc2_w, p_f2h, p_f2l, HWD, KF, KFP);
    // fc1: M=4608, N=2841, K=2880, gelu -> h hi/lo
    k_hgemm<<<dim3(23, 36), 256, SMEM_HG>>>(p_kmh, p_kml, KFP, p_f1h, p_f1l, KFP,
                                            fc1_b, nullptr, p_hh, p_hl,
                                            MROWS, KF, KFP, KFP, 1);
    // fc2: M=4608, N=2809, K=2880 -> kpT fp32 transposed
    k_hgemm<<<dim3(22, 36), 256, SMEM_HG>>>(p_hh, p_hl, KFP, p_f2h, p_f2l, KFP,
                                            fc2_b, p_kpT, nullptr, nullptr,
                                            MROWS, HWD, KFP, 0, 2);
    // score: dedicated 32x128 tile GEMM, z=6
    k_score<<<dim3(22, BT3), 256>>>();
    k_scoremax<<<dim3(NTOK, BT3), 256>>>();
    k_route<<<dim3(NTOK, BT3), 256>>>(out, outp);
}

// round 17
// speedup vs baseline: 1.2137x; 1.2126x over previous
#include <cuda_runtime.h>
#include <cuda_bf16.h>
#include <math.h>
#include <stdint.h>

#define NB     2
#define CIN    320
#define TT0    4
#define HW0    196
#define VPLANE 50176
#define VF     8
#define CDIM   768
#define TD     4
#define HH     53
#define HWD    2809
#define MPROJ  22472          // NB*TD*HWD
#define KPROJ  2304
#define NTOK   32
#define KF     2841
#define KFP    2880           // padded to multiple of 16
#define BT3    6
#define MROWS  4608           // BT3*CDIM
#define EPSBN  1e-5

// ---------------- static scratch ----------------
__device__ float  g_scaleA[CIN], g_shiftA[CIN];
__device__ float  g_v[(size_t)NB*3*VF*VPLANE];
__device__ double g_redV[3*32*2];
__device__ float  g_scaleP[3], g_shiftP[3];
__device__ float  g_xp [(size_t)MPROJ*CDIM];
__device__ float  g_pos[(size_t)MPROJ*CDIM];
__device__ double g_sumT[CDIM], g_sumsqT[CDIM], g_sumC[CDIM], g_sumsqC[CDIM];
__device__ float  g_scaleT[CDIM], g_shiftT[CDIM];
__device__ float  g_scaleC[CDIM], g_shiftC[CDIM];
__device__ float  g_d [(size_t)NB*HWD*CDIM];
__device__ float  g_sel[(size_t)NB*HWD*NTOK];
__device__ float  g_selmax[NB*NTOK];
__device__ float  g_tem [NB*NTOK*CDIM];
__device__ float  g_tsum[NB*NTOK];
__device__ float  g_hf [(size_t)MROWS*KFP];
__device__ float  g_u  [(size_t)BT3*NTOK*KFP];
__device__ float  g_score[(size_t)BT3*NTOK*HWD];
__device__ float  g_smax[BT3*NTOK];
// bf16 hi/lo operand buffers
__device__ __nv_bfloat16 g_colh[(size_t)MPROJ*KPROJ], g_coll[(size_t)MPROJ*KPROJ];
__device__ __nv_bfloat16 g_pwh[(size_t)CDIM*KPROJ],   g_pwl[(size_t)CDIM*KPROJ];
__device__ __nv_bfloat16 g_kmh[(size_t)MROWS*KFP],    g_kml[(size_t)MROWS*KFP];
__device__ __nv_bfloat16 g_f1h[(size_t)KF*KFP],       g_f1l[(size_t)KF*KFP];

// ---------------- helpers ----------------
__device__ __forceinline__ uint32_t smem_u32(const void* p) {
    uint32_t a;
    asm("{ .reg .u64 t; cvta.to.shared.u64 t, %1; cvt.u32.u64 %0, t; }" : "=r"(a) : "l"(p));
    return a;
}
__device__ __forceinline__ void ldsm4(uint32_t* r, uint32_t addr) {
    asm volatile("ldmatrix.sync.aligned.m8n8.x4.shared.b16 {%0,%1,%2,%3}, [%4];"
        : "=r"(r[0]), "=r"(r[1]), "=r"(r[2]), "=r"(r[3]) : "r"(addr));
}
__device__ __forceinline__ void mma16816(float* c, const uint32_t* a, uint32_t b0, uint32_t b1) {
    asm volatile("mma.sync.aligned.m16n8k16.row.col.f32.bf16.bf16.f32 "
        "{%0,%1,%2,%3},{%4,%5,%6,%7},{%8,%9},{%0,%1,%2,%3};"
        : "+f"(c[0]), "+f"(c[1]), "+f"(c[2]), "+f"(c[3])
        : "r"(a[0]), "r"(a[1]), "r"(a[2]), "r"(a[3]), "r"(b0), "r"(b1));
}
__device__ __forceinline__ void cpa16(uint32_t dst, const void* src, int srcsize) {
    asm volatile("cp.async.cg.shared.global [%0], [%1], 16, %2;"
        :: "r"(dst), "l"(src), "r"(srcsize) : "memory");
}
#define CP_COMMIT() asm volatile("cp.async.commit_group;" ::: "memory")
#define CP_WAIT1()  asm volatile("cp.async.wait_group 1;" ::: "memory")
#define CP_WAIT0()  asm volatile("cp.async.wait_group 0;" ::: "memory")

__device__ __forceinline__ void split_bf16(float x, __nv_bfloat16 &h, __nv_bfloat16 &l) {
    h = __float2bfloat16(x);
    l = __float2bfloat16(x - __bfloat162float(h));
}

// ================= HMMA bf16x3 GEMM (128x128 block, 64x32 warp tile, cp.async x3) =================
// mode 0: fp32 C[m*ldc+n] (+bias)            (proj)
// mode 1: bias+gelu, fp32 out at ld=ldc      (fc1 -> hf; zero-pads n in [N, ldc))
#define LDSE   24                    // smem row stride (bf16) = 48 B
#define MATB   (128*48)              // 6144 B per matrix tile
#define STGB   (4*MATB)              // 24576 B per stage
__global__ __launch_bounds__(256, 2) void k_hgemm(
    const __nv_bfloat16* __restrict__ Ah, const __nv_bfloat16* __restrict__ Al, int lda,
    const __nv_bfloat16* __restrict__ Bh, const __nv_bfloat16* __restrict__ Bl, int ldb,
    const float* __restrict__ bias, float* __restrict__ Cf,
    int M, int N, int K, int ldc, int mode)
{
    extern __shared__ char smem[];
    const uint32_t sbase = smem_u32(smem);
    const int tid = threadIdx.x;
    const int wid = tid >> 5, lane = tid & 31;
    const int m0 = blockIdx.y * 128, n0 = blockIdx.x * 128;
    const int wm = wid & 1, wn = wid >> 1;   // warp tile 64(m) x 32(n)

    // ---- loaders: mat = tid>>6 (0:Ah 1:Al 2:Bh 3:Bl), 2 rows each ----
    const int mat = tid >> 6;
    const int rr  = (tid & 63) << 1;
    const __nv_bfloat16* src; int ld, base, lim;
    if      (mat == 0) { src = Ah; ld = lda; base = m0; lim = M; }
    else if (mat == 1) { src = Al; ld = lda; base = m0; lim = M; }
    else if (mat == 2) { src = Bh; ld = ldb; base = n0; lim = N; }
    else               { src = Bl; ld = ldb; base = n0; lim = N; }
    const int sz0 = ((base + rr)     < lim) ? 16 : 0;
    const int sz1 = ((base + rr + 1) < lim) ? 16 : 0;
    const char* p0 = (const char*)(src + (size_t)(sz0 ? base + rr     : 0) * ld);
    const char* p1 = (const char*)(src + (size_t)(sz1 ? base + rr + 1 : 0) * ld);
    const uint32_t d0 = sbase + mat * MATB + rr * 48;
    const uint32_t d1 = d0 + 48;

    // ---- fragment smem offsets ----
    const uint32_t afo = (uint32_t)(((wm * 64 + (lane & 15)) * LDSE + (lane >> 4) * 8) * 2);
    const uint32_t bfo = (uint32_t)(((wn * 32 + (lane & 15)) * LDSE + (lane >> 4) * 8) * 2);

    float acc[4][4][4];
    #pragma unroll
    for (int i = 0; i < 4; i++)
        #pragma unroll
        for (int j = 0; j < 4; j++)
            #pragma unroll
            for (int q = 0; q < 4; q++) acc[i][j][q] = 0.f;

    const int KT = K >> 4;

    // prologue: stages 0 and 1
    cpa16(d0, p0, sz0); cpa16(d0 + 16, p0 + 16, sz0);
    cpa16(d1, p1, sz1); cpa16(d1 + 16, p1 + 16, sz1);
    CP_COMMIT();
    if (KT > 1) {
        cpa16(d0 + STGB, p0 + 32, sz0); cpa16(d0 + STGB + 16, p0 + 48, sz0);
        cpa16(d1 + STGB, p1 + 32, sz1); cpa16(d1 + STGB + 16, p1 + 48, sz1);
    }
    CP_COMMIT();

    int buf = 0;
    for (int kt = 0; kt < KT; kt++) {
        CP_WAIT1();
        __syncthreads();
        const uint32_t st = sbase + buf * STGB;
        uint32_t bh[2][4], bl[2][4];
        #pragma unroll
        for (int t = 0; t < 2; t++) {
            ldsm4(bh[t], st + 2*MATB + bfo + t * (16 * 48));
            ldsm4(bl[t], st + 3*MATB + bfo + t * (16 * 48));
        }
        #pragma unroll
        for (int i = 0; i < 4; i++) {
            uint32_t ah4[4], al4[4];
            ldsm4(ah4, st + afo + i * (16 * 48));
            ldsm4(al4, st + MATB + afo + i * (16 * 48));
            #pragma unroll
            for (int j = 0; j < 4; j++) {
                const int t = j >> 1, o = j & 1;
                mma16816(acc[i][j], ah4, bh[t][o], bh[t][2 + o]);
                mma16816(acc[i][j], ah4, bl[t][o], bl[t][2 + o]);
                mma16816(acc[i][j], al4, bh[t][o], bh[t][2 + o]);
            }
        }
        if (kt + 2 < KT) {
            const int nb = (buf + 2) % 3;
            const size_t ko = (size_t)(kt + 2) * 32;
            const uint32_t w0 = d0 + nb * STGB, w1 = d1 + nb * STGB;
            cpa16(w0, p0 + ko, sz0); cpa16(w0 + 16, p0 + ko + 16, sz0);
            cpa16(w1, p1 + ko, sz1); cpa16(w1 + 16, p1 + ko + 16, sz1);
        }
        CP_COMMIT();
        buf = (buf + 1) % 3;
    }
    CP_WAIT0();
    __syncthreads();

    // ---- epilogue: stage acc -> smf[128][129] ----
    float* smf = (float*)smem;
    #pragma unroll
    for (int i = 0; i < 4; i++) {
        const int mr = wm * 64 + i * 16 + (lane >> 2);
        #pragma unroll
        for (int j = 0; j < 4; j++) {
            const int nc = wn * 32 + j * 8 + (lane & 3) * 2;
            smf[mr * 129 + nc]           = acc[i][j][0];
            smf[mr * 129 + nc + 1]       = acc[i][j][1];
            smf[(mr + 8) * 129 + nc]     = acc[i][j][2];
            smf[(mr + 8) * 129 + nc + 1] = acc[i][j][3];
        }
    }
    __syncthreads();

    if (mode == 0) {
        for (int idx = tid; idx < 128 * 128; idx += 256) {
            const int mm = idx >> 7, nn = idx & 127;
            const int m = m0 + mm, n = n0 + nn;
            if (m < M && n < N)
                Cf[(size_t)m * ldc + n] = smf[mm * 129 + nn] + (bias ? bias[n] : 0.f);
        }
    } else {
        for (int idx = tid; idx < 128 * 128; idx += 256) {
            const int mm = idx >> 7, nn = idx & 127;
            const int m = m0 + mm, n = n0 + nn;
            if (m < M && n < ldc) {
                float v = 0.f;
                if (n < N) {
                    v = smf[mm * 129 + nn] + bias[n];
                    v = 0.5f * v * (1.f + erff(v * 0.70710678118654752f));
                }
                Cf[(size_t)m * ldc + n] = v;
            }
        }
    }
}

// ---------------- tsum[b][n] = sum_c tem ----------------
__global__ void k_tsum() {
    const int bn = blockIdx.x;            // 0..63
    __shared__ float sh[256];
    float s = 0.f;
    for (int c = threadIdx.x; c < CDIM; c += 256)
        s += g_tem[(size_t)bn * CDIM + c];
    sh[threadIdx.x] = s;
    __syncthreads();
    for (int o = 128; o > 0; o >>= 1) {
        if (threadIdx.x < o) sh[threadIdx.x] += sh[threadIdx.x + o];
        __syncthreads();
    }
    if (threadIdx.x == 0) g_tsum[bn] = sh[0];
}

// ---------------- u[z][n][k] = sum_c tem[b][n][c] * h[z*768+c][k] ----------------
__global__ __launch_bounds__(256) void k_u() {
    const int z = blockIdx.y, k0 = blockIdx.x * 64;
    const int b = z / 3;
    const int tid = threadIdx.x;
    const int kl = tid & 63, ng = tid >> 6;   // 4 groups of 8 n
    __shared__ float tems[32][64];
    __shared__ float hs[64][65];
    float acc[8];
    #pragma unroll
    for (int i = 0; i < 8; i++) acc[i] = 0.f;

    for (int c0 = 0; c0 < CDIM; c0 += 64) {
        __syncthreads();
        for (int i = tid; i < 32 * 64; i += 256) {
            int n = i >> 6, c = i & 63;
            tems[n][c] = g_tem[((size_t)b * NTOK + n) * CDIM + c0 + c];
        }
        for (int i = tid; i < 64 * 64; i += 256) {
            int r = i >> 6, kk = i & 63;
            hs[r][kk] = g_hf[((size_t)z * CDIM + c0 + r) * KFP + k0 + kk];
        }
        __syncthreads();
        #pragma unroll 16
        for (int cc = 0; cc < 64; cc++) {
            float hv = hs[cc][kl];
            #pragma unroll
            for (int nn = 0; nn < 8; nn++)
                acc[nn] = fmaf(tems[ng * 8 + nn][cc], hv, acc[nn]);
        }
    }
    #pragma unroll
    for (int nn = 0; nn < 8; nn++)
        g_u[((size_t)z * NTOK + ng * 8 + nn) * KFP + k0 + kl] = acc[nn];
}

// ---------------- score[z][n][hw] = sum_k u*fc2_w + tsum*fc2_b ----------------
__global__ __launch_bounds__(256) void k_scoreU(const float* __restrict__ f2w,
                                                const float* __restrict__ f2b) {
    const int z = blockIdx.y, hw0 = blockIdx.x * 64;
    const int b = z / 3;
    const int tid = threadIdx.x;
    const int hwl = tid & 63, ng = tid >> 6;   // 4 groups of 8 n
    __shared__ float us[32][64];
    __shared__ float fw[64][65];
    float acc[8];
    #pragma unroll
    for (int i = 0; i < 8; i++) acc[i] = 0.f;
    const int hw = hw0 + hwl;

    for (int k0 = 0; k0 < KFP; k0 += 64) {
        __syncthreads();
        for (int i = tid; i < 32 * 64; i += 256) {
            int n = i >> 6, kk = i & 63;
            us[n][kk] = g_u[((size_t)z * NTOK + n) * KFP + k0 + kk];
        }
        for (int i = tid; i < 64 * 64; i += 256) {
            int r = i >> 6, kk = i & 63;
            fw[r][kk] = (hw0 + r < HWD && k0 + kk < KF)
                        ? f2w[(size_t)(hw0 + r) * KF + k0 + kk] : 0.f;
        }
        __syncthreads();
        #pragma unroll 16
        for (int kk = 0; kk < 64; kk++) {
            float fv = fw[hwl][kk];
            #pragma unroll
            for (int nn = 0; nn < 8; nn++)
                acc[nn] = fmaf(us[ng * 8 + nn][kk], fv, acc[nn]);
        }
    }
    if (hw < HWD) {
        const float bb = f2b[hw];
        #pragma unroll
        for (int nn = 0; nn < 8; nn++)
            g_score[((size_t)z * NTOK + ng * 8 + nn) * HWD + hw] =
                acc[nn] + g_tsum[b * NTOK + ng * 8 + nn] * bb;
    }
}

// ---------------- zero accumulators ----------------
__global__ void k_zero() {
    int i = threadIdx.x;
    if (i < CDIM) { g_sumT[i]=0.0; g_sumsqT[i]=0.0; g_sumC[i]=0.0; g_sumsqC[i]=0.0; }
}

// ---------------- BN over x (320 ch) ----------------
__global__ void k_bn_a(const float* __restrict__ x, const float* __restrict__ g,
                       const float* __restrict__ b) {
    int c = blockIdx.x;
    double s = 0.0, s2 = 0.0;
    for (int i = threadIdx.x; i < NB*TT0*HW0; i += blockDim.x) {
        int bb = i / (TT0*HW0), r = i % (TT0*HW0);
        float v = x[((size_t)(bb*CIN + c))*(TT0*HW0) + r];
        s += v; s2 += (double)v * v;
    }
    __shared__ double sh[256], sh2[256];
    sh[threadIdx.x] = s; sh2[threadIdx.x] = s2;
    __syncthreads();
    for (int o = 128; o > 0; o >>= 1) {
        if (threadIdx.x < o) { sh[threadIdx.x] += sh[threadIdx.x+o]; sh2[threadIdx.x] += sh2[threadIdx.x+o]; }
        __syncthreads();
    }
    if (threadIdx.x == 0) {
        double n = (double)(NB*TT0*HW0);
        double mean = sh[0]/n, var = sh2[0]/n - mean*mean;
        float sc = (float)((double)g[c] / sqrt(var + EPSBN));
        g_scaleA[c] = sc;
        g_shiftA[c] = b[c] - (float)mean * sc;
    }
}

// ---------------- tconv + relu6 + residual -> g_v (8 positions/block) ----------------
__global__ __launch_bounds__(256) void k_tconv(
    const float* __restrict__ x, const float* __restrict__ tw,
    const float* __restrict__ tb, const float* __restrict__ ori) {
    __shared__ float xs[8][CIN];
    int tid = threadIdx.x;
    for (int idx = tid; idx < 8*CIN; idx += 256) {
        int p = idx / CIN, i = idx % CIN;
        int lin = blockIdx.x * 8 + p;
        int w = lin % 14, h = (lin/14) % 14, t = (lin/196) % TT0, bb = lin/(196*TT0);
        xs[p][i] = x[((size_t)(bb*CIN+i)*TT0 + t)*HW0 + h*14 + w] * g_scaleA[i] + g_shiftA[i];
    }
    __syncthreads();
    for (int jj = tid; jj < 1536; jj += 256) {
        float a[8];
        #pragma unroll
        for (int p = 0; p < 8; p++) a[p] = 0.f;
        const float* wp = tw + jj;
        #pragma unroll 4
        for (int i = 0; i < CIN; i++) {
            float wv = *wp; wp += 1536;
            #pragma unroll
            for (int p = 0; p < 8; p++) a[p] = fmaf(xs[p][i], wv, a[p]);
        }
        int o = jj >> 9, rem = jj & 511;
        int k = rem >> 8, p = (rem >> 4) & 15, q = rem & 15;
        float bias = tb[o];
        #pragma unroll
        for (int pp = 0; pp < 8; pp++) {
            int lin = blockIdx.x * 8 + pp;
            int w = lin % 14, h = (lin/14) % 14, t = (lin/196) % TT0, bb = lin/(196*TT0);
            float val = fminf(fmaxf(a[pp] + bias, 0.f), 6.f);
            size_t oidx = ((size_t)(bb*3+o)*VF + (2*t+k))*VPLANE + (16*h+p)*224 + (16*w+q);
            g_v[oidx] = val + ori[oidx];
        }
    }
}

// ---------------- BN stats of v (3 ch) ----------------
__global__ void k_bnv_part() {
    int ch = blockIdx.x, part = blockIdx.y;
    const int per = (NB*VF*VPLANE) / 32;
    double s = 0.0, s2 = 0.0;
    int base = part * per;
    for (int i = threadIdx.x; i < per; i += blockDim.x) {
        int gi = base + i;
        int b = gi / (VF*VPLANE), r = gi % (VF*VPLANE);
        float v = g_v[((size_t)(b*3+ch))*VF*VPLANE + r];
        s += v; s2 += (double)v * v;
    }
    __shared__ double sh[256], sh2[256];
    sh[threadIdx.x] = s; sh2[threadIdx.x] = s2;
    __syncthreads();
    for (int o = 128; o > 0; o >>= 1) {
        if (threadIdx.x < o) { sh[threadIdx.x] += sh[threadIdx.x+o]; sh2[threadIdx.x] += sh2[threadIdx.x+o]; }
        __syncthreads();
    }
    if (threadIdx.x == 0) { g_redV[(ch*32+part)*2] = sh[0]; g_redV[(ch*32+part)*2+1] = sh2[0]; }
}
__global__ void k_bnv_final(const float* __restrict__ g, const float* __restrict__ b) {
    int ch = blockIdx.x;
    double s  = g_redV[(ch*32 + threadIdx.x)*2];
    double s2 = g_redV[(ch*32 + threadIdx.x)*2 + 1];
    for (int o = 16; o > 0; o >>= 1) {
        s  += __shfl_down_sync(0xffffffffu, s,  o);
        s2 += __shfl_down_sync(0xffffffffu, s2, o);
    }
    if (threadIdx.x == 0) {
        double n = (double)(NB*VF*VPLANE);
        double mean = s/n, var = s2/n - mean*mean;
        float sc = (float)((double)g[ch] / sqrt(var + EPSBN));
        g_scaleP[ch] = sc;
        g_shiftP[ch] = b[ch] - (float)mean * sc;
    }
}

// ---------------- im2col -> bf16 hi/lo (BN folded, zero t-pad) ----------------
__global__ void k_im2col() {
    size_t idx = (size_t)blockIdx.x * 256 + threadIdx.x;
    if (idx >= (size_t)MPROJ * 576) return;
    int m  = (int)(idx / 576);
    int k4 = (int)(idx % 576) * 4;
    int c  = k4 / 768;
    int kt = (k4 % 768) / 256;
    int p  = (k4 % 256) / 16;
    int q  = k4 % 16;
    int w = m % HH, h = (m/HH) % HH, t = (m/HWD) % TD, b = m / (TD*HWD);
    int it = 2*t + kt - 1;
    float4 o;
    if (it < 0 || it > 7) {
        o = make_float4(0.f, 0.f, 0.f, 0.f);
    } else {
        const float* src = g_v + ((size_t)(b*3+c)*VF + it)*VPLANE + (4*h+p)*224 + (4*w+q);
        float4 v = *(const float4*)src;
        float sc = g_scaleP[c], sh = g_shiftP[c];
        o = make_float4(v.x*sc+sh, v.y*sc+sh, v.z*sc+sh, v.w*sc+sh);
    }
    __nv_bfloat16 h0,h1,h2,h3,l0,l1,l2,l3;
    split_bf16(o.x,h0,l0); split_bf16(o.y,h1,l1); split_bf16(o.z,h2,l2); split_bf16(o.w,h3,l3);
    uint2 ph, pl;
    ph.x = (uint32_t)__bfloat16_as_ushort(h0) | ((uint32_t)__bfloat16_as_ushort(h1) << 16);
    ph.y = (uint32_t)__bfloat16_as_ushort(h2) | ((uint32_t)__bfloat16_as_ushort(h3) << 16);
    pl.x = (uint32_t)__bfloat16_as_ushort(l0) | ((uint32_t)__bfloat16_as_ushort(l1) << 16);
    pl.y = (uint32_t)__bfloat16_as_ushort(l2) | ((uint32_t)__bfloat16_as_ushort(l3) << 16);
    *(uint2*)(g_colh + (size_t)m*KPROJ + k4) = ph;
    *(uint2*)(g_coll + (size_t)m*KPROJ + k4) = pl;
}

// ---------------- fp32 -> bf16 hi/lo weight convert with K padding ----------------
__global__ void k_cvtpad(const float* __restrict__ src, __nv_bfloat16* __restrict__ dh,
                         __nv_bfloat16* __restrict__ dl, int rows, int kin, int kout) {
    size_t idx = (size_t)blockIdx.x * 256 + threadIdx.x;
    if (idx >= (size_t)rows * kout) return;
    int rr = (int)(idx / kout), k = (int)(idx % kout);
    float v = (k < kin) ? src[(size_t)rr * kin + k] : 0.f;
    __nv_bfloat16 h, l; split_bf16(v, h, l);
    dh[idx] = h; dl[idx] = l;
}

// ---------------- pos conv: depthwise 3x3x3 pad 1 on raw xp ----------------
__global__ __launch_bounds__(768) void k_pos(const float* __restrict__ pw,
                                             const float* __restrict__ pb) {
    int h = blockIdx.x, t = blockIdx.y, b = blockIdx.z;
    int c = threadIdx.x;
    float w27[27];
    #pragma unroll
    for (int i = 0; i < 27; i++) w27[i] = pw[c*27 + i];
    float bias = pb[c];
    float prv[9], cur[9], nxt[9];
    #pragma unroll
    for (int j = 0; j < 9; j++) { prv[j] = 0.f; cur[j] = 0.f; }
    #pragma unroll
    for (int j = 0; j < 9; j++) {
        int dt = j/3 - 1, dh = j%3 - 1;
        int tt = t + dt, hh = h + dh;
        cur[j] = (tt >= 0 && tt < TD && hh >= 0 && hh < HH)
                 ? g_xp[(((size_t)(b*TD+tt)*HWD) + hh*HH + 0)*CDIM + c] : 0.f;
    }
    for (int w = 0; w < HH; w++) {
        #pragma unroll
        for (int j = 0; j < 9; j++) {
            int dt = j/3 - 1, dh = j%3 - 1;
            int tt = t + dt, hh = h + dh;
            nxt[j] = (w+1 < HH && tt >= 0 && tt < TD && hh >= 0 && hh < HH)
                     ? g_xp[(((size_t)(b*TD+tt)*HWD) + hh*HH + (w+1))*CDIM + c] : 0.f;
        }
        float acc = bias;
        #pragma unroll
        for (int j = 0; j < 9; j++) {
            acc = fmaf(prv[j], w27[j*3+0], acc);
            acc = fmaf(cur[j], w27[j*3+1], acc);
            acc = fmaf(nxt[j], w27[j*3+2], acc);
        }
        g_pos[(((size_t)(b*TD+t)*HWD) + h*HH + w)*CDIM + c] = acc;
        #pragma unroll
        for (int j = 0; j < 9; j++) { prv[j] = cur[j]; cur[j] = nxt[j]; }
    }
}

// ---------------- merged BN stats ----------------
__global__ void k_bnstat() {
    int tid = threadIdx.x;
    double sc_[3] = {0,0,0}, sc2[3] = {0,0,0};
    double st_[3] = {0,0,0}, st2[3] = {0,0,0};
    int r0 = blockIdx.x * 256;
    for (int i = 0; i < 256; i++) {
        int r = r0 + i;
        if (r >= MPROJ) break;
        bool isT0 = ((r / HWD) % TD) == 0;
        size_t base = (size_t)r * CDIM;
        #pragma unroll
        for (int k = 0; k < 3; k++) {
            float v = g_xp[base + tid + 256*k];
            double dv = (double)v;
            sc_[k] += dv; sc2[k] += dv * dv;
            if (isT0) { st_[k] += dv; st2[k] += dv * dv; }
        }
    }
    #pragma unroll
    for (int k = 0; k < 3; k++) {
        atomicAdd(&g_sumC[tid + 256*k],   sc_[k]);
        atomicAdd(&g_sumsqC[tid + 256*k], sc2[k]);
        atomicAdd(&g_sumT[tid + 256*k],   st_[k]);
        atomicAdd(&g_sumsqT[tid + 256*k], st2[k]);
    }
}
__global__ void k_bnfin(const float* gt, const float* bt,
                        const float* gc, const float* bc) {
    int c = threadIdx.x;
    {
        double n = (double)(NB*HWD);
        double mean = g_sumT[c]/n, var = g_sumsqT[c]/n - mean*mean;
        float sc = (float)((double)gt[c] / sqrt(var + EPSBN));
        g_scaleT[c] = sc; g_shiftT[c] = bt[c] - (float)mean * sc;
    }
    {
        double n = (double)MPROJ;
        double mean = g_sumC[c]/n, var = g_sumsqC[c]/n - mean*mean;
        float sc = (float)((double)gc[c] / sqrt(var + EPSBN));
        g_scaleC[c] = sc; g_shiftC[c] = bc[c] - (float)mean * sc;
    }
}

// ---------------- token-selector depthwise 3x3 + hardswish (BN_t inline) ----------------
__global__ __launch_bounds__(768) void k_dw(const float* __restrict__ dw,
                                            const float* __restrict__ db) {
    int h = blockIdx.x, b = blockIdx.y;
    int c = threadIdx.x;
    float w9[9];
    #pragma unroll
    for (int i = 0; i < 9; i++) w9[i] = dw[c*9 + i];
    float bias = db[c];
    const float scT = g_scaleT[c], shT = g_shiftT[c];
    const size_t xb0 = (size_t)(b*TD) * HWD;   // frame-0 base row of xp
    float prv[3], cur[3], nxt[3];
    #pragma unroll
    for (int j = 0; j < 3; j++) prv[j] = 0.f;
    #pragma unroll
    for (int j = 0; j < 3; j++) {
        int hh = h + j - 1;
        cur[j] = (hh >= 0 && hh < HH)
                 ? fmaf(g_xp[(xb0 + hh*HH + 0)*CDIM + c], scT, shT) : 0.f;
    }
    for (int w = 0; w < HH; w++) {
        #pragma unroll
        for (int j = 0; j < 3; j++) {
            int hh = h + j - 1;
            nxt[j] = (w+1 < HH && hh >= 0 && hh < HH)
                     ? fmaf(g_xp[(xb0 + hh*HH + (w+1))*CDIM + c], scT, shT) : 0.f;
        }
        float acc = bias;
        #pragma unroll
        for (int j = 0; j < 3; j++) {
            acc = fmaf(prv[j], w9[j*3+0], acc);
            acc = fmaf(cur[j], w9[j*3+1], acc);
            acc = fmaf(nxt[j], w9[j*3+2], acc);
        }
        float hs = acc * fminf(fmaxf(acc + 3.f, 0.f), 6.f) * (1.f/6.f);
        g_d[((size_t)b*HWD + h*HH + w)*CDIM + c] = hs;
        #pragma unroll
        for (int j = 0; j < 3; j++) { prv[j] = cur[j]; cur[j] = nxt[j]; }
    }
}

// ---------------- sel = pw(d) ----------------
__global__ void k_sel(const float* __restrict__ pww, const float* __restrict__ pwb) {
    int hw = blockIdx.x, b = blockIdx.y;
    __shared__ float ds[CDIM];
    for (int c = threadIdx.x; c < CDIM; c += 256)
        ds[c] = g_d[((size_t)b*HWD + hw)*CDIM + c];
    __syncthreads();
    int n = threadIdx.x >> 3, sub = threadIdx.x & 7;
    float acc = 0.f;
    for (int c = sub; c < CDIM; c += 8)
        acc = fmaf(ds[c], pww[n*CDIM + c], acc);
    acc += __shfl_xor_sync(0xffffffffu, acc, 1);
    acc += __shfl_xor_sync(0xffffffffu, acc, 2);
    acc += __shfl_xor_sync(0xffffffffu, acc, 4);
    if (sub == 0) g_sel[((size_t)b*HWD + hw)*NTOK + n] = acc + pwb[n];
}

__global__ void k_selmax() {
    int n = blockIdx.x, b = blockIdx.y;
    float m = -3.4e38f;
    for (int hw = threadIdx.x; hw < HWD; hw += 256)
        m = fmaxf(m, g_sel[((size_t)b*HWD + hw)*NTOK + n]);
    __shared__ float sh[256];
    sh[threadIdx.x] = m;
    __syncthreads();
    for (int o = 128; o > 0; o >>= 1) {
        if (threadIdx.x < o) sh[threadIdx.x] = fmaxf(sh[threadIdx.x], sh[threadIdx.x+o]);
        __syncthreads();
    }
    if (threadIdx.x == 0) g_selmax[b*NTOK + n] = sh[0];
}

// ---------------- tem gather (BN_t inline for feat) ----------------
__global__ void k_temgather(float* __restrict__ out, float* __restrict__ outp) {
    int n = blockIdx.x, b = blockIdx.y;
    __shared__ unsigned char flag[HWD];
    float mx = g_selmax[b*NTOK + n];
    for (int hw = threadIdx.x; hw < HWD; hw += 256)
        flag[hw] = (g_sel[((size_t)b*HWD + hw)*NTOK + n] == mx) ? 1 : 0;
    __syncthreads();
    int c0 = threadIdx.x, c1 = threadIdx.x + 256, c2 = threadIdx.x + 512;
    const float sc0 = g_scaleT[c0], sh0 = g_shiftT[c0];
    const float sc1 = g_scaleT[c1], sh1 = g_shiftT[c1];
    const float sc2 = g_scaleT[c2], sh2 = g_shiftT[c2];
    float a0=0,a1=0,a2=0, p0=0,p1=0,p2=0;
    for (int hw = 0; hw < HWD; hw++) {
        if (flag[hw]) {
            size_t pb = ((size_t)(b*TD)*HWD + hw)*CDIM;
            a0 += fmaf(g_xp[pb+c0], sc0, sh0);
            a1 += fmaf(g_xp[pb+c1], sc1, sh1);
            a2 += fmaf(g_xp[pb+c2], sc2, sh2);
            p0 += g_pos[pb+c0]; p1 += g_pos[pb+c1]; p2 += g_pos[pb+c2];
        }
    }
    size_t tb = ((size_t)b*NTOK + n)*CDIM;
    g_tem[tb+c0]=a0; g_tem[tb+c1]=a1; g_tem[tb+c2]=a2;
    size_t ob = ((size_t)(b*TD + 0)*NTOK + n)*CDIM;
    out[ob+c0]=a0; out[ob+c1]=a1; out[ob+c2]=a2;
    outp[ob+c0]=p0; outp[ob+c1]=p1; outp[ob+c2]=p2;
}

// ---------------- build kmat hi/lo [z*768+c][j], ld=KFP ----------------
__global__ void k_kmat() {
    int j = blockIdx.x * 128 + threadIdx.x;
    if (j >= KFP) return;
    int c = blockIdx.y, z = blockIdx.z;
    int b = z / 3, t = z % 3;
    float v;
    if (j < NTOK)      v = g_tem[((size_t)b*NTOK + j)*CDIM + c];
    else if (j < KF)   v = g_xp[((size_t)(b*TD + t + 1)*HWD + (j - NTOK))*CDIM + c]
                           * g_scaleC[c] + g_shiftC[c];
    else               v = 0.f;
    __nv_bfloat16 h, l; split_bf16(v, h, l);
    size_t o = ((size_t)z*CDIM + c)*KFP + j;
    g_kmh[o] = h; g_kml[o] = l;
}

// ---------------- score max ----------------
__global__ void k_scoremax() {
    int n = blockIdx.x, z = blockIdx.y;
    float m = -3.4e38f;
    for (int hw = threadIdx.x; hw < HWD; hw += 256)
        m = fmaxf(m, g_score[((size_t)z*NTOK + n)*HWD + hw]);
    __shared__ float sh[256];
    sh[threadIdx.x] = m;
    __syncthreads();
    for (int o = 128; o > 0; o >>= 1) {
        if (threadIdx.x < o) sh[threadIdx.x] = fmaxf(sh[threadIdx.x], sh[threadIdx.x+o]);
        __syncthreads();
    }
    if (threadIdx.x == 0) g_smax[z*NTOK + n] = sh[0];
}

// ---------------- route gather -> out frames 1..3 ----------------
__global__ void k_route(float* __restrict__ out, float* __restrict__ outp) {
    int n = blockIdx.x, z = blockIdx.y;
    int b = z / 3, t = z % 3;
    __shared__ unsigned char flag[HWD];
    float mx = g_smax[z*NTOK + n];
    for (int hw = threadIdx.x; hw < HWD; hw += 256)
        flag[hw] = (g_score[((size_t)z*NTOK + n)*HWD + hw] == mx) ? 1 : 0;
    __syncthreads();
    int c0 = threadIdx.x, c1 = threadIdx.x + 256, c2 = threadIdx.x + 512;
    float s0=0,s1=0,s2=0, p0=0,p1=0,p2=0;
    int cnt = 0;
    for (int hw = 0; hw < HWD; hw++) {
        if (flag[hw]) {
            size_t xb = ((size_t)(b*TD + t + 1)*HWD + hw)*CDIM;
            s0 += g_xp[xb+c0]; s1 += g_xp[xb+c1]; s2 += g_xp[xb+c2];
            p0 += g_pos[xb+c0]; p1 += g_pos[xb+c1]; p2 += g_pos[xb+c2];
            cnt++;
        }
    }
    float fc = (float)cnt;
    size_t ob = ((size_t)(b*TD + t + 1)*NTOK + n)*CDIM;
    out[ob+c0] = g_scaleC[c0]*s0 + fc*g_shiftC[c0];
    out[ob+c1] = g_scaleC[c1]*s1 + fc*g_shiftC[c1];
    out[ob+c2] = g_scaleC[c2]*s2 + fc*g_shiftC[c2];
    outp[ob+c0] = p0; outp[ob+c1] = p1; outp[ob+c2] = p2;
}

// ---------------- launch ----------------
extern "C" void kernel_launch(void* const* d_in, const int* in_sizes, int n_in,
                              void* d_out, int out_size) {
    const float* x       = (const float*)d_in[0];
    const float* ori     = (const float*)d_in[1];
    const float* bn_a_g  = (const float*)d_in[2];
    const float* bn_a_b  = (const float*)d_in[3];
    const float* tconv_w = (const float*)d_in[4];
    const float* tconv_b = (const float*)d_in[5];
    const float* bn_p_g  = (const float*)d_in[6];
    const float* bn_p_b  = (const float*)d_in[7];
    const float* proj_w  = (const float*)d_in[8];
    const float* proj_b  = (const float*)d_in[9];
    const float* pos_w   = (const float*)d_in[10];
    const float* pos_b   = (const float*)d_in[11];
    const float* bn_t_g  = (const float*)d_in[12];
    const float* bn_t_b  = (const float*)d_in[13];
    const float* dw_w    = (const float*)d_in[14];
    const float* dw_b    = (const float*)d_in[15];
    const float* pw_w    = (const float*)d_in[16];
    const float* pw_b    = (const float*)d_in[17];
    const float* bn_c_g  = (const float*)d_in[18];
    const float* bn_c_b  = (const float*)d_in[19];
    const float* fc1_w   = (const float*)d_in[20];
    const float* fc1_b   = (const float*)d_in[21];
    const float* fc2_w   = (const float*)d_in[22];
    const float* fc2_b   = (const float*)d_in[23];

    float* out  = (float*)d_out;
    float* outp = out + out_size / 2;

    float *p_xp, *p_hf;
    __nv_bfloat16 *p_colh, *p_coll, *p_pwh, *p_pwl, *p_kmh, *p_kml, *p_f1h, *p_f1l;
    cudaGetSymbolAddress((void**)&p_xp,    g_xp);
    cudaGetSymbolAddress((void**)&p_hf,    g_hf);
    cudaGetSymbolAddress((void**)&p_colh,  g_colh);
    cudaGetSymbolAddress((void**)&p_coll,  g_coll);
    cudaGetSymbolAddress((void**)&p_pwh,   g_pwh);
    cudaGetSymbolAddress((void**)&p_pwl,   g_pwl);
    cudaGetSymbolAddress((void**)&p_kmh,   g_kmh);
    cudaGetSymbolAddress((void**)&p_kml,   g_kml);
    cudaGetSymbolAddress((void**)&p_f1h,   g_f1h);
    cudaGetSymbolAddress((void**)&p_f1l,   g_f1l);

    const int SMEM_HG = 3 * STGB;  // 73728 B (covers 66048 B epilogue buffer)
    cudaFuncSetAttribute(k_hgemm, cudaFuncAttributeMaxDynamicSharedMemorySize, SMEM_HG);

    k_zero<<<1, 768>>>();
    k_bn_a<<<CIN, 256>>>(x, bn_a_g, bn_a_b);
    k_tconv<<<196, 256>>>(x, tconv_w, tconv_b, ori);
    k_bnv_part<<<dim3(3, 32), 256>>>();
    k_bnv_final<<<3, 32>>>(bn_p_g, bn_p_b);
    k_im2col<<<(int)(((size_t)MPROJ*576 + 255)/256), 256>>>();
    k_cvtpad<<<(int)(((size_t)CDIM*KPROJ + 255)/256), 256>>>(proj_w, p_pwh, p_pwl, CDIM, KPROJ, KPROJ);
    // proj: M=22472, N=768, K=2304 -> xp fp32
    k_hgemm<<<dim3(6, 176), 256, SMEM_HG>>>(p_colh, p_coll, KPROJ, p_pwh, p_pwl, KPROJ,
                                            proj_b, p_xp,
                                            MPROJ, CDIM, KPROJ, CDIM, 0);
    k_pos<<<dim3(HH, TD, NB), 768>>>(pos_w, pos_b);
    k_bnstat<<<88, 256>>>();
    k_bnfin<<<1, 768>>>(bn_t_g, bn_t_b, bn_c_g, bn_c_b);
    k_dw<<<dim3(HH, NB), 768>>>(dw_w, dw_b);
    k_sel<<<dim3(HWD, NB), 256>>>(pw_w, pw_b);
    k_selmax<<<dim3(NTOK, NB), 256>>>();
    k_temgather<<<dim3(NTOK, NB), 256>>>(out, outp);
    k_kmat<<<dim3((KFP+127)/128, CDIM, BT3), 128>>>();
    k_cvtpad<<<(int)(((size_t)KF*KFP + 255)/256), 256>>>(fc1_w, p_f1h, p_f1l, KF, KF, KFP);
    // fc1: M=4608, N=2841, K=2880, gelu -> hf fp32
    k_hgemm<<<dim3(23, 36), 256, SMEM_HG>>>(p_kmh, p_kml, KFP, p_f1h, p_f1l, KFP,
                                            fc1_b, p_hf,
                                            MROWS, KF, KFP, KFP, 1);
    // reassociated score path: u = tem @ h, score = u @ fc2^T + tsum*fc2_b
    k_tsum<<<NB*NTOK, 256>>>();
    k_u<<<dim3(KFP/64, BT3), 256>>>();
    k_scoreU<<<dim3((HWD + 63)/64, BT3), 256>>>(fc2_w, fc2_b);
    k_scoremax<<<dim3(NTOK, BT3), 256>>>();
    k_route<<<dim3(NTOK, BT3), 256>>>(out, outp);
}